// round 1
// baseline (speedup 1.0000x reference)
#include <cuda_runtime.h>
#include <math.h>
#include <float.h>

#define BB 2
#define SEQ 2305
#define S_IMG 2304
#define DIM 512
#define HEADS 8
#define DHEAD 64
#define ROWS (BB*SEQ)   /* 4610 */
#define GWID 48

__device__ float g_Q[ROWS*DIM];
__device__ float g_K[ROWS*DIM];
__device__ float g_V[ROWS*DIM];
__device__ float g_A[ROWS*DIM];

// ---------------- GEMM core: 64x64 tile, BK=16, 256 threads, 4x4 micro-tile ----
__device__ __forceinline__ void gemm_core(const float* __restrict__ A,
                                          const float* __restrict__ W,
                                          float* __restrict__ C,
                                          const float* __restrict__ bias,
                                          int mode) {
    __shared__ __align__(16) float As[16][68];
    __shared__ __align__(16) float Bs[16][64];
    const int tid = threadIdx.x;
    const int tx = tid & 15, ty = tid >> 4;
    const int row0 = blockIdx.x * 64;
    const int col0 = blockIdx.y * 64;
    const int lm = tid >> 2;           // 0..63 row within A tile
    const int lk = (tid & 3) * 4;      // k offset for A load
    const int bk = tid >> 4;           // 0..15 k row for B load
    const int bn = (tid & 15) * 4;     // n offset for B load
    float acc[4][4] = {};

    for (int k0 = 0; k0 < DIM; k0 += 16) {
        float4 a4;
        int ar = row0 + lm;
        if (ar < ROWS) a4 = *(const float4*)&A[(size_t)ar * DIM + k0 + lk];
        else           a4 = make_float4(0.f, 0.f, 0.f, 0.f);
        As[lk + 0][lm] = a4.x; As[lk + 1][lm] = a4.y;
        As[lk + 2][lm] = a4.z; As[lk + 3][lm] = a4.w;
        *(float4*)&Bs[bk][bn] = *(const float4*)&W[(size_t)(k0 + bk) * DIM + col0 + bn];
        __syncthreads();
#pragma unroll
        for (int kk = 0; kk < 16; kk++) {
            float4 av = *(const float4*)&As[kk][ty * 4];
            float4 bv = *(const float4*)&Bs[kk][tx * 4];
            float a[4] = {av.x, av.y, av.z, av.w};
            float b[4] = {bv.x, bv.y, bv.z, bv.w};
#pragma unroll
            for (int i = 0; i < 4; i++)
#pragma unroll
                for (int j = 0; j < 4; j++) acc[i][j] += a[i] * b[j];
        }
        __syncthreads();
    }
#pragma unroll
    for (int i = 0; i < 4; i++) {
        int r = row0 + ty * 4 + i;
        if (r >= ROWS) continue;
#pragma unroll
        for (int j = 0; j < 4; j++) {
            int c = col0 + tx * 4 + j;
            size_t o = (size_t)r * DIM + c;
            if (mode == 0) C[o] = acc[i][j];
            else           C[o] += acc[i][j] + bias[c];
        }
    }
}

__global__ void k_gemm_qkv(const float* __restrict__ X,
                           const float* __restrict__ Wq,
                           const float* __restrict__ Wk,
                           const float* __restrict__ Wv) {
    const float* W; float* C;
    if (blockIdx.z == 0)      { W = Wq; C = g_Q; }
    else if (blockIdx.z == 1) { W = Wk; C = g_K; }
    else                      { W = Wv; C = g_V; }
    gemm_core(X, W, C, nullptr, 0);
}

__global__ void k_gemm_resid(const float* __restrict__ Wo,
                             const float* __restrict__ bo,
                             float* __restrict__ X) {
    gemm_core(g_A, Wo, X, bo, 1);
}

// ---------------- Axial attention: one block per (n, head, b), length-49 causal ----
__global__ void k_axial(int typ) {
    const int n = blockIdx.x;      // 0..47
    const int head = blockIdx.y;   // 0..7
    const int b = blockIdx.z;      // 0..1
    __shared__ float Ks[49][65];
    __shared__ float Vs[49][65];
    __shared__ float Qs[2][64];
    __shared__ float sc[2][49];
    const int tid = threadIdx.x;   // 128

    // local token j: 0 = BOS(seq 0); j>=1 -> image token
    // typ0: pos = 1 + n*48 + (j-1)   (rows, attend along W)
    // typ1: pos = 1 + (j-1)*48 + n   (cols, attend along H)
    for (int idx = tid; idx < 49 * 64; idx += 128) {
        int j = idx >> 6, d = idx & 63;
        int pos = (j == 0) ? 0 : (typ == 0 ? 1 + n * GWID + (j - 1)
                                           : 1 + (j - 1) * GWID + n);
        size_t o = ((size_t)(b * SEQ + pos)) * DIM + head * DHEAD + d;
        Ks[j][d] = g_K[o];
        Vs[j][d] = g_V[o];
    }
    __syncthreads();

    const int sub = tid >> 6;   // 0/1 : two queries in flight
    const int l = tid & 63;
    for (int q0 = 0; q0 < 49; q0 += 2) {
        int qi = q0 + sub;
        bool act = (qi < 49);
        int qpos = 0;
        if (act) {
            qpos = (qi == 0) ? 0 : (typ == 0 ? 1 + n * GWID + (qi - 1)
                                             : 1 + (qi - 1) * GWID + n);
            Qs[sub][l] = g_Q[((size_t)(b * SEQ + qpos)) * DIM + head * DHEAD + l];
        }
        __syncthreads();
        if (act && l <= qi) {
            float s = 0.f;
#pragma unroll 8
            for (int d = 0; d < 64; d++) s += Qs[sub][d] * Ks[l][d];
            sc[sub][l] = s * 0.125f;
        }
        __syncthreads();
        if (act && l == 0) {
            float m = -FLT_MAX;
            for (int j = 0; j <= qi; j++) m = fmaxf(m, sc[sub][j]);
            float sum = 0.f;
            for (int j = 0; j <= qi; j++) { float pv = expf(sc[sub][j] - m); sc[sub][j] = pv; sum += pv; }
            float inv = 1.0f / sum;
            for (int j = 0; j <= qi; j++) sc[sub][j] *= inv;
        }
        __syncthreads();
        if (act && !(qi == 0 && n != 0)) {   // BOS output written only from n==0 block
            float o = 0.f;
            for (int j = 0; j <= qi; j++) o += sc[sub][j] * Vs[j][l];
            g_A[((size_t)(b * SEQ + qpos)) * DIM + head * DHEAD + l] = o;
        }
        __syncthreads();
    }
}

// ---------------- Nearby attention: analytic sparse mask, one warp per (b,head,query) ----
#define MAXSLOT 100
__global__ void k_nearby() {
    __shared__ __align__(16) float qsh[4][64];
    __shared__ float psh[4][MAXSLOT];
    __shared__ int   ksh[4][MAXSLOT];
    const int wid = threadIdx.x >> 5;
    const int lane = threadIdx.x & 31;
    const int gw = blockIdx.x * 4 + wid;
    if (gw >= BB * HEADS * SEQ) return;
    const int b = gw / (HEADS * SEQ);
    const int rem = gw % (HEADS * SEQ);
    const int head = rem / SEQ;
    const int p = rem % SEQ;
    const size_t base = ((size_t)b * SEQ) * DIM + head * DHEAD;
    float* outp = &g_A[base + (size_t)p * DIM];

    if (p == 0) {  // BOS: attends only itself
        outp[lane]      = g_V[base + lane];
        outp[lane + 32] = g_V[base + lane + 32];
        return;
    }
    const int i = p % S_IMG;  // rolled window center
    if (i == 0) {             // fully-masked row -> uniform over ALL 2305 keys
        float a0 = 0.f, a1 = 0.f;
        for (int j = 0; j < SEQ; j++) {
            a0 += g_V[base + (size_t)j * DIM + lane];
            a1 += g_V[base + (size_t)j * DIM + lane + 32];
        }
        const float inv = 1.0f / (float)SEQ;
        outp[lane] = a0 * inv; outp[lane + 32] = a1 * inv;
        return;
    }
    const int t = i >> 8, h = (i >> 4) & 15, w = i & 15;
    const int t0 = max(0, t - 3);
    const int nslots = (t - t0 + 1) * 25;

    qsh[wid][lane]      = g_Q[base + (size_t)p * DIM + lane];
    qsh[wid][lane + 32] = g_Q[base + (size_t)p * DIM + lane + 32];
    __syncwarp();

    float sloc[4];
    int cnt = 0;
    for (int slot = lane; slot < nslots; slot += 32, cnt++) {
        int f = slot / 25, r = slot % 25;
        int dh = r / 5, dw = r % 5;
        int tk = t0 + f, hk = h - 2 + dh, wk = w - 2 + dw;
        // attend iff inside grid AND (previous frame OR causal-before-center in same frame)
        bool valid = (hk >= 0 && hk < 16 && wk >= 0 && wk < 16 &&
                      (tk < t || (dh * 5 + dw) < 12));
        float s = -FLT_MAX; int kp = -1;
        if (valid) {
            kp = 1 + tk * 256 + hk * 16 + wk;
            const float4* k4 = (const float4*)&g_K[base + (size_t)kp * DIM];
            const float4* q4 = (const float4*)qsh[wid];
            float acc = 0.f;
#pragma unroll
            for (int d4 = 0; d4 < 16; d4++) {
                float4 kv = k4[d4], qv = q4[d4];
                acc += qv.x * kv.x + qv.y * kv.y + qv.z * kv.z + qv.w * kv.w;
            }
            s = acc * 0.125f;
        }
        sloc[cnt] = s;
        ksh[wid][slot] = kp;
    }
    __syncwarp();
    float m = -FLT_MAX;
    for (int c = 0; c < cnt; c++) m = fmaxf(m, sloc[c]);
    for (int off = 16; off; off >>= 1) m = fmaxf(m, __shfl_xor_sync(0xffffffffu, m, off));
    float sum = 0.f;
    cnt = 0;
    for (int slot = lane; slot < nslots; slot += 32, cnt++) {
        float pv = (ksh[wid][slot] >= 0) ? expf(sloc[cnt] - m) : 0.0f;
        psh[wid][slot] = pv;
        sum += pv;
    }
    for (int off = 16; off; off >>= 1) sum += __shfl_xor_sync(0xffffffffu, sum, off);
    const float inv = 1.0f / sum;
    __syncwarp();
    float o0 = 0.f, o1 = 0.f;
    for (int slot = 0; slot < nslots; slot++) {
        int kp = ksh[wid][slot];
        if (kp < 0) continue;           // warp-uniform branch
        float pv = psh[wid][slot];
        const float* vrow = &g_V[base + (size_t)kp * DIM];
        o0 += pv * vrow[lane];
        o1 += pv * vrow[lane + 32];
    }
    outp[lane] = o0 * inv; outp[lane + 32] = o1 * inv;
}

// ---------------- driver ----------------
extern "C" void kernel_launch(void* const* d_in, const int* in_sizes, int n_in,
                              void* d_out, int out_size) {
    const float* x = (const float*)d_in[0];
    float* X = (float*)d_out;
    cudaMemcpyAsync(X, x, sizeof(float) * (size_t)ROWS * DIM,
                    cudaMemcpyDeviceToDevice, 0);

    dim3 gq(73, 8, 3), go(73, 8, 1);
    const int nearby_blocks = (BB * HEADS * SEQ + 3) / 4;  // 9220
    for (int l = 0; l < 3; l++) {
        const float* Wq = (const float*)d_in[2 + l * 5 + 0];
        const float* Wk = (const float*)d_in[2 + l * 5 + 1];
        const float* Wv = (const float*)d_in[2 + l * 5 + 2];
        const float* Wo = (const float*)d_in[2 + l * 5 + 3];
        const float* bo = (const float*)d_in[2 + l * 5 + 4];
        k_gemm_qkv<<<gq, 256>>>(X, Wq, Wk, Wv);
        if (l < 2) k_axial<<<dim3(48, 8, 2), 128>>>(l);
        else       k_nearby<<<nearby_blocks, 128>>>();
        k_gemm_resid<<<go, 256>>>(Wo, bo, X);
    }
}

// round 3
// speedup vs baseline: 1.8891x; 1.8891x over previous
#include <cuda_runtime.h>
#include <math.h>
#include <float.h>

#define BB 2
#define SEQ 2305
#define S_IMG 2304
#define DIM 512
#define HEADS 8
#define DHEAD 64
#define ROWS (BB*SEQ)   /* 4610 */
#define GWID 48

#define BM 128
#define BN 128
#define BK 8

__device__ float g_Q[ROWS*DIM];
__device__ float g_K[ROWS*DIM];
__device__ float g_V[ROWS*DIM];
__device__ float g_A[ROWS*DIM];

// ---------------- GEMM core: 128x128 tile, BK=8, 256 threads, 8x8 micro-tile,
// ---------------- double-buffered smem, conflict-free 4+4 split LDS.128 ----
__device__ __forceinline__ void gemm128(const float* __restrict__ A,
                                        const float* __restrict__ W,
                                        float* __restrict__ C,
                                        const float* __restrict__ bias,
                                        int mode) {
    __shared__ __align__(16) float As[2][BK][BM];
    __shared__ __align__(16) float Bs[2][BK][BN];
    const int tid = threadIdx.x;
    const int tx = tid & 15, ty = tid >> 4;
    const int row0 = blockIdx.x * BM, col0 = blockIdx.y * BN;
    // A tile load: 128 rows x 8 k, each thread: 1 float4 along k
    const int ar = tid >> 1;
    const int ak = (tid & 1) * 4;
    // B tile load: 8 k x 128 n, each thread: 1 float4 along n
    const int bk = tid >> 5;
    const int bn = (tid & 31) * 4;
    const int gr = row0 + ar;
    float acc[8][8] = {};

    float4 aReg = make_float4(0.f, 0.f, 0.f, 0.f), bReg;
    if (gr < ROWS) aReg = *(const float4*)&A[(size_t)gr * DIM + ak];
    bReg = *(const float4*)&W[(size_t)bk * DIM + col0 + bn];
    As[0][ak + 0][ar] = aReg.x; As[0][ak + 1][ar] = aReg.y;
    As[0][ak + 2][ar] = aReg.z; As[0][ak + 3][ar] = aReg.w;
    *(float4*)&Bs[0][bk][bn] = bReg;
    __syncthreads();

    int buf = 0;
    for (int k0 = BK; k0 <= DIM; k0 += BK) {
        if (k0 < DIM) {
            aReg = make_float4(0.f, 0.f, 0.f, 0.f);
            if (gr < ROWS) aReg = *(const float4*)&A[(size_t)gr * DIM + k0 + ak];
            bReg = *(const float4*)&W[(size_t)(k0 + bk) * DIM + col0 + bn];
        }
#pragma unroll
        for (int kk = 0; kk < BK; kk++) {
            float4 a0 = *(const float4*)&As[buf][kk][ty * 4];
            float4 a1 = *(const float4*)&As[buf][kk][ty * 4 + 64];
            float4 b0 = *(const float4*)&Bs[buf][kk][tx * 4];
            float4 b1 = *(const float4*)&Bs[buf][kk][tx * 4 + 64];
            float a[8] = {a0.x, a0.y, a0.z, a0.w, a1.x, a1.y, a1.z, a1.w};
            float bl[8] = {b0.x, b0.y, b0.z, b0.w, b1.x, b1.y, b1.z, b1.w};
#pragma unroll
            for (int i = 0; i < 8; i++)
#pragma unroll
                for (int j = 0; j < 8; j++) acc[i][j] += a[i] * bl[j];
        }
        if (k0 < DIM) {
            buf ^= 1;
            As[buf][ak + 0][ar] = aReg.x; As[buf][ak + 1][ar] = aReg.y;
            As[buf][ak + 2][ar] = aReg.z; As[buf][ak + 3][ar] = aReg.w;
            *(float4*)&Bs[buf][bk][bn] = bReg;
            __syncthreads();
        }
    }

#pragma unroll
    for (int hi = 0; hi < 2; hi++) {
#pragma unroll
        for (int i = 0; i < 4; i++) {
            int r = row0 + hi * 64 + ty * 4 + i;
            if (r >= ROWS) continue;
#pragma unroll
            for (int hj = 0; hj < 2; hj++) {
                int c = col0 + hj * 64 + tx * 4;
                float4* outp = (float4*)&C[(size_t)r * DIM + c];
                float4 v;
                v.x = acc[hi * 4 + i][hj * 4 + 0];
                v.y = acc[hi * 4 + i][hj * 4 + 1];
                v.z = acc[hi * 4 + i][hj * 4 + 2];
                v.w = acc[hi * 4 + i][hj * 4 + 3];
                if (mode == 1) {
                    float4 old = *outp;
                    const float4 bv = *(const float4*)&bias[c];
                    v.x += old.x + bv.x; v.y += old.y + bv.y;
                    v.z += old.z + bv.z; v.w += old.w + bv.w;
                }
                *outp = v;
            }
        }
    }
}

__global__ void __launch_bounds__(256, 2)
k_gemm_qkv(const float* __restrict__ X,
           const float* __restrict__ Wq,
           const float* __restrict__ Wk,
           const float* __restrict__ Wv) {
    const float* W; float* C;
    if (blockIdx.z == 0)      { W = Wq; C = g_Q; }
    else if (blockIdx.z == 1) { W = Wk; C = g_K; }
    else                      { W = Wv; C = g_V; }
    gemm128(X, W, C, nullptr, 0);
}

__global__ void __launch_bounds__(256, 2)
k_gemm_resid(const float* __restrict__ Wo,
             const float* __restrict__ bo,
             float* __restrict__ X) {
    gemm128(g_A, Wo, X, bo, 1);
}

// ---------------- Axial attention: one block per (n, head, b), length-49 causal ----
__global__ void k_axial(int typ) {
    const int n = blockIdx.x;      // 0..47
    const int head = blockIdx.y;   // 0..7
    const int b = blockIdx.z;      // 0..1
    __shared__ float Ks[49][65];
    __shared__ float Vs[49][65];
    __shared__ float Qs[2][64];
    __shared__ float sc[2][49];
    const int tid = threadIdx.x;   // 128

    for (int idx = tid; idx < 49 * 64; idx += 128) {
        int j = idx >> 6, d = idx & 63;
        int pos = (j == 0) ? 0 : (typ == 0 ? 1 + n * GWID + (j - 1)
                                           : 1 + (j - 1) * GWID + n);
        size_t o = ((size_t)(b * SEQ + pos)) * DIM + head * DHEAD + d;
        Ks[j][d] = g_K[o];
        Vs[j][d] = g_V[o];
    }
    __syncthreads();

    const int sub = tid >> 6;   // 0/1 : two queries in flight
    const int l = tid & 63;
    for (int q0 = 0; q0 < 49; q0 += 2) {
        int qi = q0 + sub;
        bool act = (qi < 49);
        int qpos = 0;
        if (act) {
            qpos = (qi == 0) ? 0 : (typ == 0 ? 1 + n * GWID + (qi - 1)
                                             : 1 + (qi - 1) * GWID + n);
            Qs[sub][l] = g_Q[((size_t)(b * SEQ + qpos)) * DIM + head * DHEAD + l];
        }
        __syncthreads();
        if (act && l <= qi) {
            float s = 0.f;
#pragma unroll 8
            for (int d = 0; d < 64; d++) s += Qs[sub][d] * Ks[l][d];
            sc[sub][l] = s * 0.125f;
        }
        __syncthreads();
        if (act && l == 0) {
            float m = -FLT_MAX;
            for (int j = 0; j <= qi; j++) m = fmaxf(m, sc[sub][j]);
            float sum = 0.f;
            for (int j = 0; j <= qi; j++) { float pv = expf(sc[sub][j] - m); sc[sub][j] = pv; sum += pv; }
            float inv = 1.0f / sum;
            for (int j = 0; j <= qi; j++) sc[sub][j] *= inv;
        }
        __syncthreads();
        if (act && !(qi == 0 && n != 0)) {   // BOS output written only from n==0 block
            float o = 0.f;
            for (int j = 0; j <= qi; j++) o += sc[sub][j] * Vs[j][l];
            g_A[((size_t)(b * SEQ + qpos)) * DIM + head * DHEAD + l] = o;
        }
        __syncthreads();
    }
}

// ---------------- Nearby attention: analytic sparse mask, one warp per (b,head,query) ----
#define MAXSLOT 100
__global__ void k_nearby() {
    __shared__ __align__(16) float qsh[4][64];
    __shared__ float psh[4][MAXSLOT];
    __shared__ int   ksh[4][MAXSLOT];
    const int wid = threadIdx.x >> 5;
    const int lane = threadIdx.x & 31;
    const int gw = blockIdx.x * 4 + wid;
    if (gw >= BB * HEADS * SEQ) return;
    const int b = gw / (HEADS * SEQ);
    const int rem = gw % (HEADS * SEQ);
    const int head = rem / SEQ;
    const int p = rem % SEQ;
    const size_t base = ((size_t)b * SEQ) * DIM + head * DHEAD;
    float* outp = &g_A[base + (size_t)p * DIM];

    if (p == 0) {  // BOS: attends only itself
        outp[lane]      = g_V[base + lane];
        outp[lane + 32] = g_V[base + lane + 32];
        return;
    }
    const int i = p % S_IMG;  // rolled window center
    if (i == 0) {             // fully-masked row -> uniform over ALL 2305 keys
        float a0 = 0.f, a1 = 0.f;
        for (int j = 0; j < SEQ; j++) {
            a0 += g_V[base + (size_t)j * DIM + lane];
            a1 += g_V[base + (size_t)j * DIM + lane + 32];
        }
        const float inv = 1.0f / (float)SEQ;
        outp[lane] = a0 * inv; outp[lane + 32] = a1 * inv;
        return;
    }
    const int t = i >> 8, h = (i >> 4) & 15, w = i & 15;
    const int t0 = max(0, t - 3);
    const int nslots = (t - t0 + 1) * 25;

    qsh[wid][lane]      = g_Q[base + (size_t)p * DIM + lane];
    qsh[wid][lane + 32] = g_Q[base + (size_t)p * DIM + lane + 32];
    __syncwarp();

    float sloc[4];
    int cnt = 0;
    for (int slot = lane; slot < nslots; slot += 32, cnt++) {
        int f = slot / 25, r = slot % 25;
        int dh = r / 5, dw = r % 5;
        int tk = t0 + f, hk = h - 2 + dh, wk = w - 2 + dw;
        bool valid = (hk >= 0 && hk < 16 && wk >= 0 && wk < 16 &&
                      (tk < t || (dh * 5 + dw) < 12));
        float s = -FLT_MAX; int kp = -1;
        if (valid) {
            kp = 1 + tk * 256 + hk * 16 + wk;
            const float4* k4 = (const float4*)&g_K[base + (size_t)kp * DIM];
            const float4* q4 = (const float4*)qsh[wid];
            float acc = 0.f;
#pragma unroll
            for (int d4 = 0; d4 < 16; d4++) {
                float4 kv = k4[d4], qv = q4[d4];
                acc += qv.x * kv.x + qv.y * kv.y + qv.z * kv.z + qv.w * kv.w;
            }
            s = acc * 0.125f;
        }
        sloc[cnt] = s;
        ksh[wid][slot] = kp;
    }
    __syncwarp();
    float m = -FLT_MAX;
    for (int c = 0; c < cnt; c++) m = fmaxf(m, sloc[c]);
    for (int off = 16; off; off >>= 1) m = fmaxf(m, __shfl_xor_sync(0xffffffffu, m, off));
    float sum = 0.f;
    cnt = 0;
    for (int slot = lane; slot < nslots; slot += 32, cnt++) {
        float pv = (ksh[wid][slot] >= 0) ? expf(sloc[cnt] - m) : 0.0f;
        psh[wid][slot] = pv;
        sum += pv;
    }
    for (int off = 16; off; off >>= 1) sum += __shfl_xor_sync(0xffffffffu, sum, off);
    const float inv = 1.0f / sum;
    __syncwarp();
    float o0 = 0.f, o1 = 0.f;
    for (int slot = 0; slot < nslots; slot++) {
        int kp = ksh[wid][slot];
        if (kp < 0) continue;           // warp-uniform branch
        float pv = psh[wid][slot];
        const float* vrow = &g_V[base + (size_t)kp * DIM];
        o0 += pv * vrow[lane];
        o1 += pv * vrow[lane + 32];
    }
    outp[lane] = o0 * inv; outp[lane + 32] = o1 * inv;
}

// ---------------- driver ----------------
extern "C" void kernel_launch(void* const* d_in, const int* in_sizes, int n_in,
                              void* d_out, int out_size) {
    const float* x = (const float*)d_in[0];
    float* X = (float*)d_out;
    cudaMemcpyAsync(X, x, sizeof(float) * (size_t)ROWS * DIM,
                    cudaMemcpyDeviceToDevice, 0);

    dim3 gq((ROWS + BM - 1) / BM, DIM / BN, 3);   // 37 x 4 x 3
    dim3 go((ROWS + BM - 1) / BM, DIM / BN, 1);   // 37 x 4
    const int nearby_blocks = (BB * HEADS * SEQ + 3) / 4;  // 9220
    for (int l = 0; l < 3; l++) {
        const float* Wq = (const float*)d_in[2 + l * 5 + 0];
        const float* Wk = (const float*)d_in[2 + l * 5 + 1];
        const float* Wv = (const float*)d_in[2 + l * 5 + 2];
        const float* Wo = (const float*)d_in[2 + l * 5 + 3];
        const float* bo = (const float*)d_in[2 + l * 5 + 4];
        k_gemm_qkv<<<gq, 256>>>(X, Wq, Wk, Wv);
        if (l < 2) k_axial<<<dim3(48, 8, 2), 128>>>(l);
        else       k_nearby<<<nearby_blocks, 128>>>();
        k_gemm_resid<<<go, 256>>>(Wo, bo, X);
    }
}

// round 5
// speedup vs baseline: 2.4014x; 1.2712x over previous
#include <cuda_runtime.h>
#include <math.h>
#include <float.h>
#include <stdint.h>

#define BB 2
#define SEQ 2305
#define S_IMG 2304
#define DIM 512
#define HEADS 8
#define DHEAD 64
#define ROWS (BB*SEQ)   /* 4610 */
#define GWID 48

#define BM 128
#define BN 128
#define BKC 32              /* k per smem chunk */
#define NCHUNK (DIM/BKC)    /* 16 */

// tcgen05 available only in the arch-specific ('a') compilation pass.
#if !defined(__CUDA_ARCH__) || defined(__CUDA_ARCH_FEAT_SM103_ALL) || defined(__CUDA_ARCH_FEAT_SM100_ALL) || defined(__CUDA_ARCH_FEAT_SM101_ALL)
#define HAS_TCGEN05 1
#else
#define HAS_TCGEN05 0
#endif

__device__ float g_Q[ROWS*DIM];
__device__ float g_K[ROWS*DIM];
__device__ float g_V[ROWS*DIM];
__device__ float g_A[ROWS*DIM];

// SMEM layout (dynamic): [0:4) tmem ptr, [8:16) mbar, tiles @1024:
#define TILE_BYTES (128*128)          /* 16 KB per tile (128 rows x 128B) */
#define SMEM_TILE0 1024
#define SMEM_TOTAL (1024 + 4*TILE_BYTES)   /* 66560 */

#if HAS_TCGEN05
// ---------------- tcgen05 helpers ----------------
__device__ __forceinline__ uint32_t smem_u32(const void* p) {
    uint32_t a;
    asm("{ .reg .u64 t; cvta.to.shared.u64 t, %1; cvt.u32.u64 %0, t; }" : "=r"(a) : "l"(p));
    return a;
}
__device__ __forceinline__ uint32_t elect_one() {
    uint32_t p;
    asm volatile("{ .reg .pred p; elect.sync _|p, 0xFFFFFFFF; selp.b32 %0,1,0,p; }" : "=r"(p));
    return p;
}
static __device__ __forceinline__ uint64_t make_desc(uint32_t addr) {
    // SW128, Blackwell v1, LBO=1 (16B), SBO=64 (1024B)
    const uint64_t base = (uint64_t(2) << 61) | (uint64_t(1) << 46) |
                          (uint64_t(64) << 32) | (uint64_t(1) << 16);
    return base | ((uint64_t)(addr >> 4) & 0x3FFF);
}
// idesc: c=F32(1@4), a=TF32(2@7), b=TF32(2@10), N/8@17, M/16@24
#define IDESC_TF32 ((1u<<4) | (2u<<7) | (2u<<10) | ((BN/8u)<<17) | ((BM/16u)<<24))

__device__ __forceinline__ void mma_tf32(uint32_t d_tmem, uint64_t a_desc,
                                         uint64_t b_desc, uint32_t en) {
    asm volatile(
        "{\n\t.reg .pred p;\n\t"
        "setp.ne.u32 p, %4, 0;\n\t"
        "tcgen05.mma.cta_group::1.kind::tf32 [%0], %1, %2, %3, {%5,%5,%5,%5}, p;\n\t}"
        :: "r"(d_tmem), "l"(a_desc), "l"(b_desc), "r"(IDESC_TF32), "r"(en), "r"(0u)
        : "memory");
}
#define MBAR_INIT(a,c)  asm volatile("mbarrier.init.shared.b64 [%0], %1;" :: "r"(a), "r"(c) : "memory")
#define MBAR_INVAL(a)   asm volatile("mbarrier.inval.shared.b64 [%0];" :: "r"(a) : "memory")
#define COMMIT_CG1(a)   asm volatile("tcgen05.commit.cta_group::1.mbarrier::arrive::one.shared::cluster.b64 [%0];" :: "r"(a) : "memory")
__device__ __forceinline__ void mbar_wait(uint32_t addr, uint32_t parity) {
    asm volatile(
        "{\n\t.reg .pred P1;\n\t"
        "WL_%=:\n\t"
        "mbarrier.try_wait.parity.acquire.cta.shared::cta.b64 P1, [%0], %1, 0x989680;\n\t"
        "@P1 bra.uni WD_%=;\n\t"
        "bra.uni WL_%=;\n\t"
        "WD_%=:\n\t}"
        :: "r"(addr), "r"(parity) : "memory");
}
#define FENCE_ASYNC()   asm volatile("fence.proxy.async.shared::cta;" ::: "memory")
#define TC_ALLOC(sp,n)  asm volatile("tcgen05.alloc.cta_group::1.sync.aligned.shared::cta.b32 [%0], %1;" :: "r"(sp), "r"(n) : "memory")
#define TC_DEALLOC(t,n) asm volatile("tcgen05.dealloc.cta_group::1.sync.aligned.b32 %0, %1;" :: "r"(t), "r"(n))
#define TC_FENCE_AFTER()  asm volatile("tcgen05.fence::after_thread_sync;" ::: "memory")
#define TC_FENCE_BEFORE() asm volatile("tcgen05.fence::before_thread_sync;" ::: "memory")
#define TC_WAIT_LD()      asm volatile("tcgen05.wait::ld.sync.aligned;" ::: "memory")
#define LDTM_X32(r, a) \
    asm volatile("tcgen05.ld.sync.aligned.32x32b.x32.b32 " \
        "{%0,%1,%2,%3,%4,%5,%6,%7,%8,%9,%10,%11,%12,%13,%14,%15," \
        "%16,%17,%18,%19,%20,%21,%22,%23,%24,%25,%26,%27,%28,%29,%30,%31}, [%32];" \
        : "=r"((r)[0]),"=r"((r)[1]),"=r"((r)[2]),"=r"((r)[3]),"=r"((r)[4]),"=r"((r)[5]),"=r"((r)[6]),"=r"((r)[7]), \
          "=r"((r)[8]),"=r"((r)[9]),"=r"((r)[10]),"=r"((r)[11]),"=r"((r)[12]),"=r"((r)[13]),"=r"((r)[14]),"=r"((r)[15]), \
          "=r"((r)[16]),"=r"((r)[17]),"=r"((r)[18]),"=r"((r)[19]),"=r"((r)[20]),"=r"((r)[21]),"=r"((r)[22]),"=r"((r)[23]), \
          "=r"((r)[24]),"=r"((r)[25]),"=r"((r)[26]),"=r"((r)[27]),"=r"((r)[28]),"=r"((r)[29]),"=r"((r)[30]),"=r"((r)[31]) \
        : "r"(a))

__device__ __forceinline__ uint32_t sw128(uint32_t off) {
    return off ^ ((off >> 3) & 0x70);
}

// Load one 128x32 A chunk + 32x128 (transposed->[n][k]) B chunk into buffers.
__device__ __forceinline__ void load_tiles(const float* __restrict__ A,
                                           const float* __restrict__ W,
                                           int row0, int col0, int kbase,
                                           char* bufA, char* bufB, int tid) {
    // A: thread -> row = tid>>1, k-half = (tid&1)*16 ; 4 x float4
    {
        const int row = tid >> 1;
        const int kh = (tid & 1) * 16;
        const int gr = row0 + row;
        float4 a[4];
        if (gr < ROWS) {
            const float4* src = (const float4*)&A[(size_t)gr * DIM + kbase + kh];
            a[0] = src[0]; a[1] = src[1]; a[2] = src[2]; a[3] = src[3];
        } else {
            a[0] = a[1] = a[2] = a[3] = make_float4(0.f, 0.f, 0.f, 0.f);
        }
#pragma unroll
        for (int i = 0; i < 4; i++) {
            uint32_t off = sw128((uint32_t)(row * 128 + (kh + i * 4) * 4));
            *(float4*)(bufA + off) = a[i];
        }
    }
    // B: thread -> k = tid>>3, n0 = (tid&7)*16 ; read W[k][n] coalesced, scatter to [n][k]
    {
        const int k = tid >> 3;
        const int n0 = (tid & 7) * 16;
        const float4* src = (const float4*)&W[(size_t)(kbase + k) * DIM + col0 + n0];
#pragma unroll
        for (int i = 0; i < 4; i++) {
            float4 w = src[i];
            const int n = n0 + i * 4;
            *(float*)(bufB + sw128((uint32_t)((n + 0) * 128 + k * 4))) = w.x;
            *(float*)(bufB + sw128((uint32_t)((n + 1) * 128 + k * 4))) = w.y;
            *(float*)(bufB + sw128((uint32_t)((n + 2) * 128 + k * 4))) = w.z;
            *(float*)(bufB + sw128((uint32_t)((n + 3) * 128 + k * 4))) = w.w;
        }
    }
}

// ---------------- tcgen05 tf32 GEMM: C[128x128] tile = A[128xK] * W[KxN] ----
__device__ __forceinline__ void gemm_tc(const float* __restrict__ A,
                                        const float* __restrict__ W,
                                        float* __restrict__ C,
                                        const float* __restrict__ bias,
                                        int mode) {
    extern __shared__ char smem[];
    const int tid = threadIdx.x;
    const int wid = tid >> 5;
    const int lane = tid & 31;
    const int row0 = blockIdx.x * BM, col0 = blockIdx.y * BN;
    const uint32_t sbase = smem_u32(smem);
    const uint32_t mbar = sbase + 8;

    if (wid == 0) TC_ALLOC(sbase, 128);
    if (tid == 0) MBAR_INIT(mbar, 1);
    __syncthreads();
    uint32_t tmem;
    asm volatile("ld.shared.b32 %0, [%1];" : "=r"(tmem) : "r"(sbase));

    char* bufA[2] = { smem + SMEM_TILE0,                  smem + SMEM_TILE0 + 2 * TILE_BYTES };
    char* bufB[2] = { smem + SMEM_TILE0 + TILE_BYTES,     smem + SMEM_TILE0 + 3 * TILE_BYTES };

    load_tiles(A, W, row0, col0, 0, bufA[0], bufB[0], tid);
    FENCE_ASYNC();
    __syncthreads();

    for (int c = 0; c < NCHUNK; c++) {
        const int p = c & 1;
        if (wid == 0) {
            if (elect_one()) {
                uint64_t ad = make_desc(sbase + SMEM_TILE0 + (p ? 2 * TILE_BYTES : 0));
                uint64_t bd = make_desc(sbase + SMEM_TILE0 + (p ? 3 * TILE_BYTES : TILE_BYTES));
#pragma unroll
                for (int s = 0; s < 4; s++)
                    mma_tf32(tmem, ad + s * 2, bd + s * 2, (uint32_t)(c * 4 + s > 0));
                COMMIT_CG1(mbar);
            }
        }
        if (c + 1 < NCHUNK)
            load_tiles(A, W, row0, col0, (c + 1) * BKC, bufA[1 - p], bufB[1 - p], tid);
        FENCE_ASYNC();
        mbar_wait(mbar, (uint32_t)p);
        __syncthreads();
    }

    TC_FENCE_AFTER();
    if (wid < 4) {
        const int r = row0 + wid * 32 + lane;
#pragma unroll
        for (int cb = 0; cb < 4; cb++) {
            uint32_t rg[32];
            LDTM_X32(rg, tmem + cb * 32);
            TC_WAIT_LD();
            if (r < ROWS) {
                float* outp = &C[(size_t)r * DIM + col0 + cb * 32];
#pragma unroll
                for (int j = 0; j < 8; j++) {
                    float4 v;
                    v.x = __uint_as_float(rg[j * 4 + 0]);
                    v.y = __uint_as_float(rg[j * 4 + 1]);
                    v.z = __uint_as_float(rg[j * 4 + 2]);
                    v.w = __uint_as_float(rg[j * 4 + 3]);
                    if (mode == 1) {
                        float4 old = *(float4*)&outp[j * 4];
                        const float4 bv = *(const float4*)&bias[col0 + cb * 32 + j * 4];
                        v.x += old.x + bv.x; v.y += old.y + bv.y;
                        v.z += old.z + bv.z; v.w += old.w + bv.w;
                    }
                    *(float4*)&outp[j * 4] = v;
                }
            }
        }
    }
    TC_FENCE_BEFORE();
    __syncthreads();
    if (tid == 0) MBAR_INVAL(mbar);
    if (wid == 0) TC_DEALLOC(tmem, 128);
}

#else  /* !HAS_TCGEN05: SIMT fallback (round-2 GEMM) for the non-'a' PTX pass */

#define FBK 8
__device__ __forceinline__ void gemm_tc(const float* __restrict__ A,
                                        const float* __restrict__ W,
                                        float* __restrict__ C,
                                        const float* __restrict__ bias,
                                        int mode) {
    __shared__ __align__(16) float As[2][FBK][BM];
    __shared__ __align__(16) float Bs[2][FBK][BN];
    const int tid = threadIdx.x;
    const int tx = tid & 15, ty = tid >> 4;
    const int row0 = blockIdx.x * BM, col0 = blockIdx.y * BN;
    const int ar = tid >> 1;
    const int ak = (tid & 1) * 4;
    const int bk = tid >> 5;
    const int bn = (tid & 31) * 4;
    const int gr = row0 + ar;
    float acc[8][8] = {};

    float4 aReg = make_float4(0.f, 0.f, 0.f, 0.f), bReg;
    if (gr < ROWS) aReg = *(const float4*)&A[(size_t)gr * DIM + ak];
    bReg = *(const float4*)&W[(size_t)bk * DIM + col0 + bn];
    As[0][ak + 0][ar] = aReg.x; As[0][ak + 1][ar] = aReg.y;
    As[0][ak + 2][ar] = aReg.z; As[0][ak + 3][ar] = aReg.w;
    *(float4*)&Bs[0][bk][bn] = bReg;
    __syncthreads();

    int buf = 0;
    for (int k0 = FBK; k0 <= DIM; k0 += FBK) {
        if (k0 < DIM) {
            aReg = make_float4(0.f, 0.f, 0.f, 0.f);
            if (gr < ROWS) aReg = *(const float4*)&A[(size_t)gr * DIM + k0 + ak];
            bReg = *(const float4*)&W[(size_t)(k0 + bk) * DIM + col0 + bn];
        }
#pragma unroll
        for (int kk = 0; kk < FBK; kk++) {
            float4 a0 = *(const float4*)&As[buf][kk][ty * 4];
            float4 a1 = *(const float4*)&As[buf][kk][ty * 4 + 64];
            float4 b0 = *(const float4*)&Bs[buf][kk][tx * 4];
            float4 b1 = *(const float4*)&Bs[buf][kk][tx * 4 + 64];
            float a[8] = {a0.x, a0.y, a0.z, a0.w, a1.x, a1.y, a1.z, a1.w};
            float bl[8] = {b0.x, b0.y, b0.z, b0.w, b1.x, b1.y, b1.z, b1.w};
#pragma unroll
            for (int i = 0; i < 8; i++)
#pragma unroll
                for (int j = 0; j < 8; j++) acc[i][j] += a[i] * bl[j];
        }
        if (k0 < DIM) {
            buf ^= 1;
            As[buf][ak + 0][ar] = aReg.x; As[buf][ak + 1][ar] = aReg.y;
            As[buf][ak + 2][ar] = aReg.z; As[buf][ak + 3][ar] = aReg.w;
            *(float4*)&Bs[buf][bk][bn] = bReg;
            __syncthreads();
        }
    }
#pragma unroll
    for (int hi = 0; hi < 2; hi++) {
#pragma unroll
        for (int i = 0; i < 4; i++) {
            int r = row0 + hi * 64 + ty * 4 + i;
            if (r >= ROWS) continue;
#pragma unroll
            for (int hj = 0; hj < 2; hj++) {
                int c = col0 + hj * 64 + tx * 4;
                float4* outp = (float4*)&C[(size_t)r * DIM + c];
                float4 v;
                v.x = acc[hi * 4 + i][hj * 4 + 0];
                v.y = acc[hi * 4 + i][hj * 4 + 1];
                v.z = acc[hi * 4 + i][hj * 4 + 2];
                v.w = acc[hi * 4 + i][hj * 4 + 3];
                if (mode == 1) {
                    float4 old = *outp;
                    const float4 bv = *(const float4*)&bias[c];
                    v.x += old.x + bv.x; v.y += old.y + bv.y;
                    v.z += old.z + bv.z; v.w += old.w + bv.w;
                }
                *outp = v;
            }
        }
    }
}
#endif  /* HAS_TCGEN05 */

__global__ void k_gemm_qkv(const float* __restrict__ X,
                           const float* __restrict__ Wq,
                           const float* __restrict__ Wk,
                           const float* __restrict__ Wv) {
    const float* W; float* C;
    if (blockIdx.z == 0)      { W = Wq; C = g_Q; }
    else if (blockIdx.z == 1) { W = Wk; C = g_K; }
    else                      { W = Wv; C = g_V; }
    gemm_tc(X, W, C, nullptr, 0);
}

__global__ void k_gemm_resid(const float* __restrict__ Wo,
                             const float* __restrict__ bo,
                             float* __restrict__ X) {
    gemm_tc(g_A, Wo, X, bo, 1);
}

// ---------------- Axial attention: one block per (n, head, b), length-49 causal ----
__global__ void k_axial(int typ) {
    const int n = blockIdx.x;      // 0..47
    const int head = blockIdx.y;   // 0..7
    const int b = blockIdx.z;      // 0..1
    __shared__ float Ks[49][65];
    __shared__ float Vs[49][65];
    __shared__ float Qs[2][64];
    __shared__ float sc[2][49];
    const int tid = threadIdx.x;   // 128

    for (int idx = tid; idx < 49 * 64; idx += 128) {
        int j = idx >> 6, d = idx & 63;
        int pos = (j == 0) ? 0 : (typ == 0 ? 1 + n * GWID + (j - 1)
                                           : 1 + (j - 1) * GWID + n);
        size_t o = ((size_t)(b * SEQ + pos)) * DIM + head * DHEAD + d;
        Ks[j][d] = g_K[o];
        Vs[j][d] = g_V[o];
    }
    __syncthreads();

    const int sub = tid >> 6;
    const int l = tid & 63;
    for (int q0 = 0; q0 < 49; q0 += 2) {
        int qi = q0 + sub;
        bool act = (qi < 49);
        int qpos = 0;
        if (act) {
            qpos = (qi == 0) ? 0 : (typ == 0 ? 1 + n * GWID + (qi - 1)
                                             : 1 + (qi - 1) * GWID + n);
            Qs[sub][l] = g_Q[((size_t)(b * SEQ + qpos)) * DIM + head * DHEAD + l];
        }
        __syncthreads();
        if (act && l <= qi) {
            float s = 0.f;
#pragma unroll 8
            for (int d = 0; d < 64; d++) s += Qs[sub][d] * Ks[l][d];
            sc[sub][l] = s * 0.125f;
        }
        __syncthreads();
        if (act && l == 0) {
            float m = -FLT_MAX;
            for (int j = 0; j <= qi; j++) m = fmaxf(m, sc[sub][j]);
            float sum = 0.f;
            for (int j = 0; j <= qi; j++) { float pv = expf(sc[sub][j] - m); sc[sub][j] = pv; sum += pv; }
            float inv = 1.0f / sum;
            for (int j = 0; j <= qi; j++) sc[sub][j] *= inv;
        }
        __syncthreads();
        if (act && !(qi == 0 && n != 0)) {
            float o = 0.f;
            for (int j = 0; j <= qi; j++) o += sc[sub][j] * Vs[j][l];
            g_A[((size_t)(b * SEQ + qpos)) * DIM + head * DHEAD + l] = o;
        }
        __syncthreads();
    }
}

// ---------------- Nearby attention: analytic sparse mask, one warp per (b,head,query) ----
#define MAXSLOT 100
__global__ void k_nearby() {
    __shared__ __align__(16) float qsh[4][64];
    __shared__ float psh[4][MAXSLOT];
    __shared__ int   ksh[4][MAXSLOT];
    const int wid = threadIdx.x >> 5;
    const int lane = threadIdx.x & 31;
    const int gw = blockIdx.x * 4 + wid;
    if (gw >= BB * HEADS * SEQ) return;
    const int b = gw / (HEADS * SEQ);
    const int rem = gw % (HEADS * SEQ);
    const int head = rem / SEQ;
    const int p = rem % SEQ;
    const size_t base = ((size_t)b * SEQ) * DIM + head * DHEAD;
    float* outp = &g_A[base + (size_t)p * DIM];

    if (p == 0) {
        outp[lane]      = g_V[base + lane];
        outp[lane + 32] = g_V[base + lane + 32];
        return;
    }
    const int i = p % S_IMG;
    if (i == 0) {
        float a0 = 0.f, a1 = 0.f;
        for (int j = 0; j < SEQ; j++) {
            a0 += g_V[base + (size_t)j * DIM + lane];
            a1 += g_V[base + (size_t)j * DIM + lane + 32];
        }
        const float inv = 1.0f / (float)SEQ;
        outp[lane] = a0 * inv; outp[lane + 32] = a1 * inv;
        return;
    }
    const int t = i >> 8, h = (i >> 4) & 15, w = i & 15;
    const int t0 = max(0, t - 3);
    const int nslots = (t - t0 + 1) * 25;

    qsh[wid][lane]      = g_Q[base + (size_t)p * DIM + lane];
    qsh[wid][lane + 32] = g_Q[base + (size_t)p * DIM + lane + 32];
    __syncwarp();

    float sloc[4];
    int cnt = 0;
    for (int slot = lane; slot < nslots; slot += 32, cnt++) {
        int f = slot / 25, r = slot % 25;
        int dh = r / 5, dw = r % 5;
        int tk = t0 + f, hk = h - 2 + dh, wk = w - 2 + dw;
        bool valid = (hk >= 0 && hk < 16 && wk >= 0 && wk < 16 &&
                      (tk < t || (dh * 5 + dw) < 12));
        float s = -FLT_MAX; int kp = -1;
        if (valid) {
            kp = 1 + tk * 256 + hk * 16 + wk;
            const float4* k4 = (const float4*)&g_K[base + (size_t)kp * DIM];
            const float4* q4 = (const float4*)qsh[wid];
            float acc = 0.f;
#pragma unroll
            for (int d4 = 0; d4 < 16; d4++) {
                float4 kv = k4[d4], qv = q4[d4];
                acc += qv.x * kv.x + qv.y * kv.y + qv.z * kv.z + qv.w * kv.w;
            }
            s = acc * 0.125f;
        }
        sloc[cnt] = s;
        ksh[wid][slot] = kp;
    }
    __syncwarp();
    float m = -FLT_MAX;
    for (int c = 0; c < cnt; c++) m = fmaxf(m, sloc[c]);
    for (int off = 16; off; off >>= 1) m = fmaxf(m, __shfl_xor_sync(0xffffffffu, m, off));
    float sum = 0.f;
    cnt = 0;
    for (int slot = lane; slot < nslots; slot += 32, cnt++) {
        float pv = (ksh[wid][slot] >= 0) ? expf(sloc[cnt] - m) : 0.0f;
        psh[wid][slot] = pv;
        sum += pv;
    }
    for (int off = 16; off; off >>= 1) sum += __shfl_xor_sync(0xffffffffu, sum, off);
    const float inv = 1.0f / sum;
    __syncwarp();
    float o0 = 0.f, o1 = 0.f;
    for (int slot = 0; slot < nslots; slot++) {
        int kp = ksh[wid][slot];
        if (kp < 0) continue;
        float pv = psh[wid][slot];
        const float* vrow = &g_V[base + (size_t)kp * DIM];
        o0 += pv * vrow[lane];
        o1 += pv * vrow[lane + 32];
    }
    outp[lane] = o0 * inv; outp[lane + 32] = o1 * inv;
}

// ---------------- driver ----------------
extern "C" void kernel_launch(void* const* d_in, const int* in_sizes, int n_in,
                              void* d_out, int out_size) {
    const float* x = (const float*)d_in[0];
    float* X = (float*)d_out;

    static int configured = 0;
    if (!configured) {
        cudaFuncSetAttribute(k_gemm_qkv, cudaFuncAttributeMaxDynamicSharedMemorySize, SMEM_TOTAL);
        cudaFuncSetAttribute(k_gemm_resid, cudaFuncAttributeMaxDynamicSharedMemorySize, SMEM_TOTAL);
        configured = 1;
    }

    cudaMemcpyAsync(X, x, sizeof(float) * (size_t)ROWS * DIM,
                    cudaMemcpyDeviceToDevice, 0);

    dim3 gq((ROWS + BM - 1) / BM, DIM / BN, 3);   // 37 x 4 x 3
    dim3 go((ROWS + BM - 1) / BM, DIM / BN, 1);   // 37 x 4
    const int nearby_blocks = (BB * HEADS * SEQ + 3) / 4;  // 9220
    for (int l = 0; l < 3; l++) {
        const float* Wq = (const float*)d_in[2 + l * 5 + 0];
        const float* Wk = (const float*)d_in[2 + l * 5 + 1];
        const float* Wv = (const float*)d_in[2 + l * 5 + 2];
        const float* Wo = (const float*)d_in[2 + l * 5 + 3];
        const float* bo = (const float*)d_in[2 + l * 5 + 4];
        k_gemm_qkv<<<gq, 256, SMEM_TOTAL>>>(X, Wq, Wk, Wv);
        if (l < 2) k_axial<<<dim3(48, 8, 2), 128>>>(l);
        else       k_nearby<<<nearby_blocks, 128>>>();
        k_gemm_resid<<<go, 256, SMEM_TOTAL>>>(Wo, bo, X);
    }
}

// round 6
// speedup vs baseline: 2.9429x; 1.2255x over previous
#include <cuda_runtime.h>
#include <math.h>
#include <float.h>
#include <stdint.h>

#define BB 2
#define SEQ 2305
#define S_IMG 2304
#define DIM 512
#define HEADS 8
#define DHEAD 64
#define ROWS (BB*SEQ)   /* 4610 */
#define GWID 48

#define BM 128
#define BN 128
#define BKC 32              /* k per smem chunk */
#define NCHUNK (DIM/BKC)    /* 16 */

// tcgen05 available only in the arch-specific ('a') compilation pass.
#if !defined(__CUDA_ARCH__) || defined(__CUDA_ARCH_FEAT_SM103_ALL) || defined(__CUDA_ARCH_FEAT_SM100_ALL) || defined(__CUDA_ARCH_FEAT_SM101_ALL)
#define HAS_TCGEN05 1
#else
#define HAS_TCGEN05 0
#endif

__device__ float g_Q[ROWS*DIM];
__device__ float g_K[ROWS*DIM];
__device__ float g_V[ROWS*DIM];
__device__ float g_A[ROWS*DIM];
__device__ float g_Wt[12*DIM*DIM];   /* transposed weights [n][k] */

// GEMM smem: [0:4) tmem ptr, [8:16) mbar0, [16:24) mbar1, stages @1024
#define STAGE_BYTES 32768             /* 16KB A + 16KB B */
#define SMEM_TILE0 1024
#define SMEM_TOTAL (1024 + 2*STAGE_BYTES)   /* 66560 */

__device__ __forceinline__ uint32_t sw128(uint32_t off) {
    return off ^ ((off >> 3) & 0x70);
}

// ---------------- weight transpose: g_Wt[m][n][k] = W_m[k][n] ----------------
__global__ void k_transpose(const float* w0, const float* w1, const float* w2,
                            const float* w3, const float* w4, const float* w5,
                            const float* w6, const float* w7, const float* w8,
                            const float* w9, const float* w10, const float* w11) {
    const float* ws[12] = {w0,w1,w2,w3,w4,w5,w6,w7,w8,w9,w10,w11};
    const float* W = ws[blockIdx.z];
    float* out = g_Wt + (size_t)blockIdx.z * DIM * DIM;
    __shared__ float t[32][33];
    const int nx = blockIdx.x * 32, ky = blockIdx.y * 32;
#pragma unroll
    for (int j = 0; j < 4; j++) {
        int k = ky + threadIdx.y + j * 8;
        t[threadIdx.y + j * 8][threadIdx.x] = W[(size_t)k * DIM + nx + threadIdx.x];
    }
    __syncthreads();
#pragma unroll
    for (int j = 0; j < 4; j++) {
        int n = nx + threadIdx.y + j * 8;
        out[(size_t)n * DIM + ky + threadIdx.x] = t[threadIdx.x][threadIdx.y + j * 8];
    }
}

#if HAS_TCGEN05
// ---------------- tcgen05 helpers ----------------
__device__ __forceinline__ uint32_t smem_u32(const void* p) {
    uint32_t a;
    asm("{ .reg .u64 t; cvta.to.shared.u64 t, %1; cvt.u32.u64 %0, t; }" : "=r"(a) : "l"(p));
    return a;
}
__device__ __forceinline__ uint32_t elect_one() {
    uint32_t p;
    asm volatile("{ .reg .pred p; elect.sync _|p, 0xFFFFFFFF; selp.b32 %0,1,0,p; }" : "=r"(p));
    return p;
}
static __device__ __forceinline__ uint64_t make_desc(uint32_t addr) {
    const uint64_t base = (uint64_t(2) << 61) | (uint64_t(1) << 46) |
                          (uint64_t(64) << 32) | (uint64_t(1) << 16);
    return base | ((uint64_t)(addr >> 4) & 0x3FFF);
}
#define IDESC_TF32 ((1u<<4) | (2u<<7) | (2u<<10) | ((BN/8u)<<17) | ((BM/16u)<<24))

__device__ __forceinline__ void mma_tf32(uint32_t d_tmem, uint64_t a_desc,
                                         uint64_t b_desc, uint32_t en) {
    asm volatile(
        "{\n\t.reg .pred p;\n\t"
        "setp.ne.u32 p, %4, 0;\n\t"
        "tcgen05.mma.cta_group::1.kind::tf32 [%0], %1, %2, %3, {%5,%5,%5,%5}, p;\n\t}"
        :: "r"(d_tmem), "l"(a_desc), "l"(b_desc), "r"(IDESC_TF32), "r"(en), "r"(0u)
        : "memory");
}
#define MBAR_INIT(a,c)  asm volatile("mbarrier.init.shared.b64 [%0], %1;" :: "r"(a), "r"(c) : "memory")
#define MBAR_INVAL(a)   asm volatile("mbarrier.inval.shared.b64 [%0];" :: "r"(a) : "memory")
#define COMMIT_CG1(a)   asm volatile("tcgen05.commit.cta_group::1.mbarrier::arrive::one.shared::cluster.b64 [%0];" :: "r"(a) : "memory")
__device__ __forceinline__ void mbar_wait(uint32_t addr, uint32_t parity) {
    asm volatile(
        "{\n\t.reg .pred P1;\n\t"
        "WL_%=:\n\t"
        "mbarrier.try_wait.parity.acquire.cta.shared::cta.b64 P1, [%0], %1, 0x989680;\n\t"
        "@P1 bra.uni WD_%=;\n\t"
        "bra.uni WL_%=;\n\t"
        "WD_%=:\n\t}"
        :: "r"(addr), "r"(parity) : "memory");
}
#define FENCE_ASYNC()   asm volatile("fence.proxy.async.shared::cta;" ::: "memory")
#define TC_ALLOC(sp,n)  asm volatile("tcgen05.alloc.cta_group::1.sync.aligned.shared::cta.b32 [%0], %1;" :: "r"(sp), "r"(n) : "memory")
#define TC_DEALLOC(t,n) asm volatile("tcgen05.dealloc.cta_group::1.sync.aligned.b32 %0, %1;" :: "r"(t), "r"(n))
#define TC_FENCE_AFTER()  asm volatile("tcgen05.fence::after_thread_sync;" ::: "memory")
#define TC_FENCE_BEFORE() asm volatile("tcgen05.fence::before_thread_sync;" ::: "memory")
#define TC_WAIT_LD()      asm volatile("tcgen05.wait::ld.sync.aligned;" ::: "memory")
#define LDTM_X32(r, a) \
    asm volatile("tcgen05.ld.sync.aligned.32x32b.x32.b32 " \
        "{%0,%1,%2,%3,%4,%5,%6,%7,%8,%9,%10,%11,%12,%13,%14,%15," \
        "%16,%17,%18,%19,%20,%21,%22,%23,%24,%25,%26,%27,%28,%29,%30,%31}, [%32];" \
        : "=r"((r)[0]),"=r"((r)[1]),"=r"((r)[2]),"=r"((r)[3]),"=r"((r)[4]),"=r"((r)[5]),"=r"((r)[6]),"=r"((r)[7]), \
          "=r"((r)[8]),"=r"((r)[9]),"=r"((r)[10]),"=r"((r)[11]),"=r"((r)[12]),"=r"((r)[13]),"=r"((r)[14]),"=r"((r)[15]), \
          "=r"((r)[16]),"=r"((r)[17]),"=r"((r)[18]),"=r"((r)[19]),"=r"((r)[20]),"=r"((r)[21]),"=r"((r)[22]),"=r"((r)[23]), \
          "=r"((r)[24]),"=r"((r)[25]),"=r"((r)[26]),"=r"((r)[27]),"=r"((r)[28]),"=r"((r)[29]),"=r"((r)[30]),"=r"((r)[31]) \
        : "r"(a))
#define CP_A16(d,s) asm volatile("cp.async.cg.shared.global [%0], [%1], 16;" :: "r"(d), "l"(s) : "memory")
#define CP_COMMIT() asm volatile("cp.async.commit_group;" ::: "memory")
#define CP_WAIT0()  asm volatile("cp.async.wait_group 0;" ::: "memory")

// Load one 128x32 A chunk + 128x32 Bt chunk (both K-contiguous) into stage s.
__device__ __forceinline__ void load_stage(const float* __restrict__ A,
                                           const float* __restrict__ Bt,
                                           int row0, int col0, int kbase,
                                           uint32_t sb32, char* sb,
                                           int arow, int aseg) {
#pragma unroll
    for (int u = 0; u < 4; u++) {
        const int row = arow + 32 * u;
        const uint32_t off = sw128((uint32_t)(row * 128 + aseg * 16));
        const int gr = row0 + row;
        if (gr < ROWS) {
            CP_A16(sb32 + off, &A[(size_t)gr * DIM + kbase + aseg * 4]);
        } else {
            *(float4*)(sb + off) = make_float4(0.f, 0.f, 0.f, 0.f);
        }
        CP_A16(sb32 + 16384 + off, &Bt[(size_t)(col0 + row) * DIM + kbase + aseg * 4]);
    }
}

// ---------------- tcgen05 tf32 GEMM: C[128x128] tile = A[128xK] * Bt[N][K]^T ----
__device__ __forceinline__ void gemm_tc(const float* __restrict__ A,
                                        const float* __restrict__ Bt,
                                        float* __restrict__ C,
                                        const float* __restrict__ bias,
                                        int mode) {
    extern __shared__ char smem[];
    const int tid = threadIdx.x;
    const int wid = tid >> 5;
    const int lane = tid & 31;
    const int row0 = blockIdx.x * BM, col0 = blockIdx.y * BN;
    const uint32_t sbase = smem_u32(smem);
    const int arow = tid >> 3, aseg = tid & 7;

    if (wid == 0) TC_ALLOC(sbase, 128);
    if (tid == 0) { MBAR_INIT(sbase + 8, 1); MBAR_INIT(sbase + 16, 1); }
    __syncthreads();
    uint32_t tmem;
    asm volatile("ld.shared.b32 %0, [%1];" : "=r"(tmem) : "r"(sbase));

    load_stage(A, Bt, row0, col0, 0, sbase + SMEM_TILE0, smem + SMEM_TILE0, arow, aseg);
    CP_COMMIT();

    for (int c = 0; c < NCHUNK; c++) {
        const int p = c & 1;
        CP_WAIT0();
        __syncthreads();
        FENCE_ASYNC();
        if (wid == 0 && elect_one()) {
            uint64_t ad = make_desc(sbase + SMEM_TILE0 + p * STAGE_BYTES);
            uint64_t bd = make_desc(sbase + SMEM_TILE0 + p * STAGE_BYTES + 16384);
#pragma unroll
            for (int s = 0; s < 4; s++)
                mma_tf32(tmem, ad + s * 2, bd + s * 2, (uint32_t)(c * 4 + s > 0));
            COMMIT_CG1(sbase + 8 + (c & 1) * 8);
        }
        if (c + 1 < NCHUNK) {
            if (c >= 1) {
                const int m = c - 1;   // wait commit m before overwriting its buffer
                mbar_wait(sbase + 8 + (m & 1) * 8, (uint32_t)((m >> 1) & 1));
            }
            const int np = (c + 1) & 1;
            load_stage(A, Bt, row0, col0, (c + 1) * BKC,
                       sbase + SMEM_TILE0 + np * STAGE_BYTES,
                       smem + SMEM_TILE0 + np * STAGE_BYTES, arow, aseg);
            CP_COMMIT();
        }
    }
    {
        const int m = NCHUNK - 1;
        mbar_wait(sbase + 8 + (m & 1) * 8, (uint32_t)((m >> 1) & 1));
    }

    TC_FENCE_AFTER();
    if (wid < 4) {
        const int r = row0 + wid * 32 + lane;
#pragma unroll
        for (int cb = 0; cb < 4; cb++) {
            uint32_t rg[32];
            LDTM_X32(rg, tmem + cb * 32);
            TC_WAIT_LD();
            if (r < ROWS) {
                float* outp = &C[(size_t)r * DIM + col0 + cb * 32];
#pragma unroll
                for (int j = 0; j < 8; j++) {
                    float4 v;
                    v.x = __uint_as_float(rg[j * 4 + 0]);
                    v.y = __uint_as_float(rg[j * 4 + 1]);
                    v.z = __uint_as_float(rg[j * 4 + 2]);
                    v.w = __uint_as_float(rg[j * 4 + 3]);
                    if (mode == 1) {
                        float4 old = *(float4*)&outp[j * 4];
                        const float4 bv = *(const float4*)&bias[col0 + cb * 32 + j * 4];
                        v.x += old.x + bv.x; v.y += old.y + bv.y;
                        v.z += old.z + bv.z; v.w += old.w + bv.w;
                    }
                    *(float4*)&outp[j * 4] = v;
                }
            }
        }
    }
    TC_FENCE_BEFORE();
    __syncthreads();
    if (tid == 0) { MBAR_INVAL(sbase + 8); MBAR_INVAL(sbase + 16); }
    if (wid == 0) TC_DEALLOC(tmem, 128);
}

#else  /* !HAS_TCGEN05: simple correct fallback (never executed on GB300) */

__device__ __forceinline__ void gemm_tc(const float* __restrict__ A,
                                        const float* __restrict__ Bt,
                                        float* __restrict__ C,
                                        const float* __restrict__ bias,
                                        int mode) {
    const int tid = threadIdx.x;
    const int row0 = blockIdx.x * BM, col0 = blockIdx.y * BN;
    const int r = row0 + (tid >> 1);
    const int c0 = col0 + (tid & 1) * 64;
    if (r >= ROWS) return;
    for (int cc = 0; cc < 64; cc++) {
        int c = c0 + cc;
        float s = 0.f;
        for (int k = 0; k < DIM; k++) s += A[(size_t)r * DIM + k] * Bt[(size_t)c * DIM + k];
        size_t o = (size_t)r * DIM + c;
        if (mode == 0) C[o] = s;
        else           C[o] += s + bias[c];
    }
}
#endif  /* HAS_TCGEN05 */

__global__ void k_gemm_qkv(const float* __restrict__ X, int layer) {
    const float* Bt; float* C;
    const float* base = g_Wt + (size_t)layer * 4 * DIM * DIM;
    if (blockIdx.z == 0)      { Bt = base;                 C = g_Q; }
    else if (blockIdx.z == 1) { Bt = base + DIM * DIM;     C = g_K; }
    else                      { Bt = base + 2 * DIM * DIM; C = g_V; }
    gemm_tc(X, Bt, C, nullptr, 0);
}

__global__ void k_gemm_resid(int layer, const float* __restrict__ bo,
                             float* __restrict__ X) {
    const float* Bt = g_Wt + ((size_t)layer * 4 + 3) * DIM * DIM;
    gemm_tc(g_A, Bt, X, bo, 1);
}

// ---------------- Axial attention (unchanged) ----------------
__global__ void k_axial(int typ) {
    const int n = blockIdx.x;
    const int head = blockIdx.y;
    const int b = blockIdx.z;
    __shared__ float Ks[49][65];
    __shared__ float Vs[49][65];
    __shared__ float Qs[2][64];
    __shared__ float sc[2][49];
    const int tid = threadIdx.x;

    for (int idx = tid; idx < 49 * 64; idx += 128) {
        int j = idx >> 6, d = idx & 63;
        int pos = (j == 0) ? 0 : (typ == 0 ? 1 + n * GWID + (j - 1)
                                           : 1 + (j - 1) * GWID + n);
        size_t o = ((size_t)(b * SEQ + pos)) * DIM + head * DHEAD + d;
        Ks[j][d] = g_K[o];
        Vs[j][d] = g_V[o];
    }
    __syncthreads();

    const int sub = tid >> 6;
    const int l = tid & 63;
    for (int q0 = 0; q0 < 49; q0 += 2) {
        int qi = q0 + sub;
        bool act = (qi < 49);
        int qpos = 0;
        if (act) {
            qpos = (qi == 0) ? 0 : (typ == 0 ? 1 + n * GWID + (qi - 1)
                                             : 1 + (qi - 1) * GWID + n);
            Qs[sub][l] = g_Q[((size_t)(b * SEQ + qpos)) * DIM + head * DHEAD + l];
        }
        __syncthreads();
        if (act && l <= qi) {
            float s = 0.f;
#pragma unroll 8
            for (int d = 0; d < 64; d++) s += Qs[sub][d] * Ks[l][d];
            sc[sub][l] = s * 0.125f;
        }
        __syncthreads();
        if (act && l == 0) {
            float m = -FLT_MAX;
            for (int j = 0; j <= qi; j++) m = fmaxf(m, sc[sub][j]);
            float sum = 0.f;
            for (int j = 0; j <= qi; j++) { float pv = expf(sc[sub][j] - m); sc[sub][j] = pv; sum += pv; }
            float inv = 1.0f / sum;
            for (int j = 0; j <= qi; j++) sc[sub][j] *= inv;
        }
        __syncthreads();
        if (act && !(qi == 0 && n != 0)) {
            float o = 0.f;
            for (int j = 0; j <= qi; j++) o += sc[sub][j] * Vs[j][l];
            g_A[((size_t)(b * SEQ + qpos)) * DIM + head * DHEAD + l] = o;
        }
        __syncthreads();
    }
}

// ---------------- Nearby attention, tiled: CTA = (b, head, t, 2-row h-band) ----
// smem: K[384][65], V[384][65], q[8][64], p[8][128], rows[8][128]
#define KSTRIDE 65
#define NB_KOFF 0
#define NB_VOFF (384*KSTRIDE)              /* 24960 */
#define NB_QOFF (2*384*KSTRIDE)            /* 49920 */
#define NB_POFF (NB_QOFF + 8*64)           /* 50432 */
#define NB_ROFF (NB_POFF + 8*128)          /* 51456 */
#define NB_SMEM_FLOATS (NB_ROFF + 8*128)   /* 52480 */
#define NB_SMEM_BYTES (NB_SMEM_FLOATS*4)   /* 209920 */

__global__ void k_nearby_t() {
    extern __shared__ float sm[];
    const int tid = threadIdx.x;
    const int wid = tid >> 5;
    const int lane = tid & 31;
    const int t = blockIdx.y;
    const int h0 = blockIdx.x * 2;
    const int b = blockIdx.z >> 3;
    const int head = blockIdx.z & 7;
    const size_t base = ((size_t)b * SEQ) * DIM + head * DHEAD;
    const int t0 = max(0, t - 3);
    const int nf = t - t0 + 1;

    // ---- stage K/V window: rows (f, hloc 0..5, wk 0..15), hk = h0-2+hloc ----
    const int nchunks = nf * 96 * 16;
    for (int idx = tid; idx < nchunks; idx += 256) {
        const int row = idx >> 4, c4 = idx & 15;
        const int f = row / 96, rem = row % 96;
        const int hloc = rem >> 4, wk = rem & 15;
        const int hk = h0 - 2 + hloc;
        if (hk >= 0 && hk < 16) {
            const int kp = 1 + (t0 + f) * 256 + hk * 16 + wk;
            const size_t go = base + (size_t)kp * DIM + c4 * 4;
            float4 kv = *(const float4*)&g_K[go];
            float4 vv = *(const float4*)&g_V[go];
            float* kd = &sm[NB_KOFF + row * KSTRIDE + c4 * 4];
            float* vd = &sm[NB_VOFF + row * KSTRIDE + c4 * 4];
            kd[0] = kv.x; kd[1] = kv.y; kd[2] = kv.z; kd[3] = kv.w;
            vd[0] = vv.x; vd[1] = vv.y; vd[2] = vv.z; vd[3] = vv.w;
        }
    }
    __syncthreads();

    float* qsh = &sm[NB_QOFF + wid * 64];
    float* psh = &sm[NB_POFF + wid * 128];
    int*   rsh = (int*)&sm[NB_ROFF + wid * 128];

    for (int j = 0; j < 4; j++) {
        const int q = wid + 8 * j;              // 0..31
        const int qh_off = q >> 4, qw = q & 15;
        const int h = h0 + qh_off;
        const int i = t * 256 + h * 16 + qw;

        if (i == 0) {
            // specials for this (b,head): p=0 BOS self-copy; p=2304 uniform mean
            sm[0] = sm[0];  // no-op
            float* out0 = &g_A[base];
            out0[lane]      = g_V[base + lane];
            out0[lane + 32] = g_V[base + lane + 32];
            float a0 = 0.f, a1 = 0.f;
            for (int r = 0; r < SEQ; r++) {
                a0 += g_V[base + (size_t)r * DIM + lane];
                a1 += g_V[base + (size_t)r * DIM + lane + 32];
            }
            const float inv = 1.0f / (float)SEQ;
            float* outU = &g_A[base + (size_t)S_IMG * DIM];
            outU[lane]      = a0 * inv;
            outU[lane + 32] = a1 * inv;
            continue;
        }
        const int p = i;
        qsh[lane]      = g_Q[base + (size_t)p * DIM + lane];
        qsh[lane + 32] = g_Q[base + (size_t)p * DIM + lane + 32];
        __syncwarp();

        const int nslots = nf * 25;
        float sloc[4]; int myrow[4];
#pragma unroll
        for (int s = 0; s < 4; s++) {
            const int slot = lane + 32 * s;
            float sc = -FLT_MAX; int r = -1;
            if (slot < nslots) {
                const int f = slot / 25, rr = slot % 25;
                const int dh = rr / 5, dw = rr % 5;
                const int tk = t0 + f;
                const int hk = h - 2 + dh, wk = qw - 2 + dw;
                if (hk >= 0 && hk < 16 && wk >= 0 && wk < 16 &&
                    (tk < t || rr < 12)) {
                    r = f * 96 + (qh_off + dh) * 16 + wk;
                    const float* kr = &sm[NB_KOFF + r * KSTRIDE];
                    float acc = 0.f;
#pragma unroll 16
                    for (int d = 0; d < 64; d++) acc += qsh[d] * kr[d];
                    sc = acc * 0.125f;
                }
            }
            sloc[s] = sc; myrow[s] = r;
            if (slot < 128) rsh[slot] = r;
        }
        float m = fmaxf(fmaxf(sloc[0], sloc[1]), fmaxf(sloc[2], sloc[3]));
        for (int off = 16; off; off >>= 1) m = fmaxf(m, __shfl_xor_sync(0xffffffffu, m, off));
        float sum = 0.f;
#pragma unroll
        for (int s = 0; s < 4; s++) {
            const int slot = lane + 32 * s;
            float pv = (myrow[s] >= 0) ? expf(sloc[s] - m) : 0.0f;
            if (slot < 128) psh[slot] = pv;
            sum += pv;
        }
        for (int off = 16; off; off >>= 1) sum += __shfl_xor_sync(0xffffffffu, sum, off);
        const float inv = 1.0f / sum;
        __syncwarp();

        float o0 = 0.f, o1 = 0.f;
        for (int slot = 0; slot < nslots; slot++) {
            const int r = rsh[slot];
            if (r < 0) continue;
            const float pv = psh[slot];
            const float* vr = &sm[NB_VOFF + r * KSTRIDE];
            o0 += pv * vr[lane];
            o1 += pv * vr[lane + 32];
        }
        g_A[base + (size_t)p * DIM + lane]      = o0 * inv;
        g_A[base + (size_t)p * DIM + lane + 32] = o1 * inv;
        __syncwarp();
    }
}

// ---------------- driver ----------------
extern "C" void kernel_launch(void* const* d_in, const int* in_sizes, int n_in,
                              void* d_out, int out_size) {
    const float* x = (const float*)d_in[0];
    float* X = (float*)d_out;

    static int configured = 0;
    if (!configured) {
        cudaFuncSetAttribute(k_gemm_qkv, cudaFuncAttributeMaxDynamicSharedMemorySize, SMEM_TOTAL);
        cudaFuncSetAttribute(k_gemm_resid, cudaFuncAttributeMaxDynamicSharedMemorySize, SMEM_TOTAL);
        cudaFuncSetAttribute(k_nearby_t, cudaFuncAttributeMaxDynamicSharedMemorySize, NB_SMEM_BYTES);
        configured = 1;
    }

    cudaMemcpyAsync(X, x, sizeof(float) * (size_t)ROWS * DIM,
                    cudaMemcpyDeviceToDevice, 0);

    // transpose all 12 weight matrices up front (order: per layer Wq,Wk,Wv,Wo)
    k_transpose<<<dim3(16, 16, 12), dim3(32, 8)>>>(
        (const float*)d_in[2],  (const float*)d_in[3],  (const float*)d_in[4],  (const float*)d_in[5],
        (const float*)d_in[7],  (const float*)d_in[8],  (const float*)d_in[9],  (const float*)d_in[10],
        (const float*)d_in[12], (const float*)d_in[13], (const float*)d_in[14], (const float*)d_in[15]);

    dim3 gq((ROWS + BM - 1) / BM, DIM / BN, 3);   // 37 x 4 x 3
    dim3 go((ROWS + BM - 1) / BM, DIM / BN, 1);   // 37 x 4
    for (int l = 0; l < 3; l++) {
        const float* bo = (const float*)d_in[2 + l * 5 + 4];
        k_gemm_qkv<<<gq, 256, SMEM_TOTAL>>>(X, l);
        if (l < 2) k_axial<<<dim3(48, 8, 2), 128>>>(l);
        else       k_nearby_t<<<dim3(8, 9, 16), 256, NB_SMEM_BYTES>>>();
        k_gemm_resid<<<go, 256, SMEM_TOTAL>>>(l, bo, X);
    }
}

// round 9
// speedup vs baseline: 3.7698x; 1.2810x over previous
#include <cuda_runtime.h>
#include <math.h>
#include <float.h>
#include <stdint.h>

#define BB 2
#define SEQ 2305
#define S_IMG 2304
#define DIM 512
#define HEADS 8
#define DHEAD 64
#define ROWS (BB*SEQ)   /* 4610 */
#define GWID 48

#define BM 128
#define BN 128
#define BKC 32              /* k per smem chunk */
#define NCHUNK (DIM/BKC)    /* 16 */
#define NSTAGE 4

// tcgen05 available only in the arch-specific ('a') compilation pass.
#if !defined(__CUDA_ARCH__) || defined(__CUDA_ARCH_FEAT_SM103_ALL) || defined(__CUDA_ARCH_FEAT_SM100_ALL) || defined(__CUDA_ARCH_FEAT_SM101_ALL)
#define HAS_TCGEN05 1
#else
#define HAS_TCGEN05 0
#endif

__device__ float g_Q[ROWS*DIM];
__device__ float g_K[ROWS*DIM];
__device__ float g_V[ROWS*DIM];
__device__ float g_A[ROWS*DIM];
__device__ float g_Wt[12*DIM*DIM];   /* transposed weights [n][k] */

// GEMM smem: [0:4) tmem ptr, [8:40) 4 mbars, stages @1024
#define STAGE_BYTES 32768             /* 16KB A + 16KB B */
#define SMEM_TILE0 1024
#define SMEM_TOTAL (1024 + NSTAGE*STAGE_BYTES)   /* 132096 */

__device__ __forceinline__ uint32_t sw128(uint32_t off) {
    return off ^ ((off >> 3) & 0x70);
}

// ---------------- weight transpose: g_Wt[m][n][k] = W_m[k][n] ----------------
__global__ void k_transpose(const float* w0, const float* w1, const float* w2,
                            const float* w3, const float* w4, const float* w5,
                            const float* w6, const float* w7, const float* w8,
                            const float* w9, const float* w10, const float* w11) {
    const float* ws[12] = {w0,w1,w2,w3,w4,w5,w6,w7,w8,w9,w10,w11};
    const float* W = ws[blockIdx.z];
    float* out = g_Wt + (size_t)blockIdx.z * DIM * DIM;
    __shared__ float t[32][33];
    const int nx = blockIdx.x * 32, ky = blockIdx.y * 32;
#pragma unroll
    for (int j = 0; j < 4; j++) {
        int k = ky + threadIdx.y + j * 8;
        t[threadIdx.y + j * 8][threadIdx.x] = W[(size_t)k * DIM + nx + threadIdx.x];
    }
    __syncthreads();
#pragma unroll
    for (int j = 0; j < 4; j++) {
        int n = nx + threadIdx.y + j * 8;
        out[(size_t)n * DIM + ky + threadIdx.x] = t[threadIdx.x][threadIdx.y + j * 8];
    }
}

#if HAS_TCGEN05
// ---------------- tcgen05 helpers ----------------
__device__ __forceinline__ uint32_t smem_u32(const void* p) {
    uint32_t a;
    asm("{ .reg .u64 t; cvta.to.shared.u64 t, %1; cvt.u32.u64 %0, t; }" : "=r"(a) : "l"(p));
    return a;
}
__device__ __forceinline__ uint32_t elect_one() {
    uint32_t p;
    asm volatile("{ .reg .pred p; elect.sync _|p, 0xFFFFFFFF; selp.b32 %0,1,0,p; }" : "=r"(p));
    return p;
}
static __device__ __forceinline__ uint64_t make_desc(uint32_t addr) {
    const uint64_t base = (uint64_t(2) << 61) | (uint64_t(1) << 46) |
                          (uint64_t(64) << 32) | (uint64_t(1) << 16);
    return base | ((uint64_t)(addr >> 4) & 0x3FFF);
}
#define IDESC_TF32 ((1u<<4) | (2u<<7) | (2u<<10) | ((BN/8u)<<17) | ((BM/16u)<<24))

__device__ __forceinline__ void mma_tf32(uint32_t d_tmem, uint64_t a_desc,
                                         uint64_t b_desc, uint32_t en) {
    asm volatile(
        "{\n\t.reg .pred p;\n\t"
        "setp.ne.u32 p, %4, 0;\n\t"
        "tcgen05.mma.cta_group::1.kind::tf32 [%0], %1, %2, %3, {%5,%5,%5,%5}, p;\n\t}"
        :: "r"(d_tmem), "l"(a_desc), "l"(b_desc), "r"(IDESC_TF32), "r"(en), "r"(0u)
        : "memory");
}
#define MBAR_INIT(a,c)  asm volatile("mbarrier.init.shared.b64 [%0], %1;" :: "r"(a), "r"(c) : "memory")
#define MBAR_INVAL(a)   asm volatile("mbarrier.inval.shared.b64 [%0];" :: "r"(a) : "memory")
#define COMMIT_CG1(a)   asm volatile("tcgen05.commit.cta_group::1.mbarrier::arrive::one.shared::cluster.b64 [%0];" :: "r"(a) : "memory")
__device__ __forceinline__ void mbar_wait(uint32_t addr, uint32_t parity) {
    asm volatile(
        "{\n\t.reg .pred P1;\n\t"
        "WL_%=:\n\t"
        "mbarrier.try_wait.parity.acquire.cta.shared::cta.b64 P1, [%0], %1, 0x989680;\n\t"
        "@P1 bra.uni WD_%=;\n\t"
        "bra.uni WL_%=;\n\t"
        "WD_%=:\n\t}"
        :: "r"(addr), "r"(parity) : "memory");
}
#define FENCE_ASYNC()   asm volatile("fence.proxy.async.shared::cta;" ::: "memory")
#define TC_ALLOC(sp,n)  asm volatile("tcgen05.alloc.cta_group::1.sync.aligned.shared::cta.b32 [%0], %1;" :: "r"(sp), "r"(n) : "memory")
#define TC_DEALLOC(t,n) asm volatile("tcgen05.dealloc.cta_group::1.sync.aligned.b32 %0, %1;" :: "r"(t), "r"(n))
#define TC_FENCE_AFTER()  asm volatile("tcgen05.fence::after_thread_sync;" ::: "memory")
#define TC_FENCE_BEFORE() asm volatile("tcgen05.fence::before_thread_sync;" ::: "memory")
#define TC_WAIT_LD()      asm volatile("tcgen05.wait::ld.sync.aligned;" ::: "memory")
#define LDTM_X32(r, a) \
    asm volatile("tcgen05.ld.sync.aligned.32x32b.x32.b32 " \
        "{%0,%1,%2,%3,%4,%5,%6,%7,%8,%9,%10,%11,%12,%13,%14,%15," \
        "%16,%17,%18,%19,%20,%21,%22,%23,%24,%25,%26,%27,%28,%29,%30,%31}, [%32];" \
        : "=r"((r)[0]),"=r"((r)[1]),"=r"((r)[2]),"=r"((r)[3]),"=r"((r)[4]),"=r"((r)[5]),"=r"((r)[6]),"=r"((r)[7]), \
          "=r"((r)[8]),"=r"((r)[9]),"=r"((r)[10]),"=r"((r)[11]),"=r"((r)[12]),"=r"((r)[13]),"=r"((r)[14]),"=r"((r)[15]), \
          "=r"((r)[16]),"=r"((r)[17]),"=r"((r)[18]),"=r"((r)[19]),"=r"((r)[20]),"=r"((r)[21]),"=r"((r)[22]),"=r"((r)[23]), \
          "=r"((r)[24]),"=r"((r)[25]),"=r"((r)[26]),"=r"((r)[27]),"=r"((r)[28]),"=r"((r)[29]),"=r"((r)[30]),"=r"((r)[31]) \
        : "r"(a))
#define CP_A16(d,s) asm volatile("cp.async.cg.shared.global [%0], [%1], 16;" :: "r"(d), "l"(s) : "memory")
#define CP_COMMIT() asm volatile("cp.async.commit_group;" ::: "memory")
#define CP_WAIT2()  asm volatile("cp.async.wait_group 2;" ::: "memory")

// Load one 128x32 A chunk + 128x32 Bt chunk (both K-contiguous) into a stage.
__device__ __forceinline__ void load_stage(const float* __restrict__ A,
                                           const float* __restrict__ Bt,
                                           int row0, int col0, int kbase,
                                           uint32_t sb32, char* sb,
                                           int arow, int aseg) {
#pragma unroll
    for (int u = 0; u < 4; u++) {
        const int row = arow + 32 * u;
        const uint32_t off = sw128((uint32_t)(row * 128 + aseg * 16));
        const int gr = row0 + row;
        if (gr < ROWS) {
            CP_A16(sb32 + off, &A[(size_t)gr * DIM + kbase + aseg * 4]);
        } else {
            *(float4*)(sb + off) = make_float4(0.f, 0.f, 0.f, 0.f);
        }
        CP_A16(sb32 + 16384 + off, &Bt[(size_t)(col0 + row) * DIM + kbase + aseg * 4]);
    }
}

// ---------------- tcgen05 tf32 GEMM, 4-deep cp.async pipeline ----------------
__device__ __forceinline__ void gemm_tc(const float* __restrict__ A,
                                        const float* __restrict__ Bt,
                                        float* __restrict__ C,
                                        const float* __restrict__ bias,
                                        int mode) {
    extern __shared__ char smem[];
    const int tid = threadIdx.x;
    const int wid = tid >> 5;
    const int lane = tid & 31;
    const int row0 = blockIdx.x * BM, col0 = blockIdx.y * BN;
    const uint32_t sbase = smem_u32(smem);
    const int arow = tid >> 3, aseg = tid & 7;

    if (wid == 0) TC_ALLOC(sbase, 128);
    if (tid == 0) {
#pragma unroll
        for (int s = 0; s < NSTAGE; s++) MBAR_INIT(sbase + 8 + s * 8, 1);
    }
    __syncthreads();
    uint32_t tmem;
    asm volatile("ld.shared.b32 %0, [%1];" : "=r"(tmem) : "r"(sbase));

    // prologue: stages 0..2 in flight (one commit group each)
#pragma unroll
    for (int s = 0; s < 3; s++) {
        load_stage(A, Bt, row0, col0, s * BKC,
                   sbase + SMEM_TILE0 + s * STAGE_BYTES,
                   smem + SMEM_TILE0 + s * STAGE_BYTES, arow, aseg);
        CP_COMMIT();
    }

    for (int c = 0; c < NCHUNK; c++) {
        CP_WAIT2();                 // stage c's group retired
        __syncthreads();
        FENCE_ASYNC();
        if (wid == 0 && elect_one()) {
            const int buf = c & 3;
            uint64_t ad = make_desc(sbase + SMEM_TILE0 + buf * STAGE_BYTES);
            uint64_t bd = make_desc(sbase + SMEM_TILE0 + buf * STAGE_BYTES + 16384);
#pragma unroll
            for (int s = 0; s < 4; s++)
                mma_tf32(tmem, ad + s * 2, bd + s * 2, (uint32_t)(c * 4 + s > 0));
            COMMIT_CG1(sbase + 8 + buf * 8);
        }
        if (c + 3 < NCHUNK) {
            if (c >= 1)   // buffer (c+3)&3 was used by MMA chunk c-1
                mbar_wait(sbase + 8 + ((c - 1) & 3) * 8, (uint32_t)(((c - 1) >> 2) & 1));
            const int nb = (c + 3) & 3;
            load_stage(A, Bt, row0, col0, (c + 3) * BKC,
                       sbase + SMEM_TILE0 + nb * STAGE_BYTES,
                       smem + SMEM_TILE0 + nb * STAGE_BYTES, arow, aseg);
        }
        CP_COMMIT();                // empty group when no load: keeps wait_group 2 exact
    }
    // final commit completion implies all prior MMAs done (in-order)
    mbar_wait(sbase + 8 + ((NCHUNK - 1) & 3) * 8, (uint32_t)(((NCHUNK - 1) >> 2) & 1));

    TC_FENCE_AFTER();
    if (wid < 4) {
        const int r = row0 + wid * 32 + lane;
#pragma unroll
        for (int cb = 0; cb < 4; cb++) {
            uint32_t rg[32];
            LDTM_X32(rg, tmem + cb * 32);
            TC_WAIT_LD();
            if (r < ROWS) {
                float* outp = &C[(size_t)r * DIM + col0 + cb * 32];
#pragma unroll
                for (int j = 0; j < 8; j++) {
                    float4 v;
                    v.x = __uint_as_float(rg[j * 4 + 0]);
                    v.y = __uint_as_float(rg[j * 4 + 1]);
                    v.z = __uint_as_float(rg[j * 4 + 2]);
                    v.w = __uint_as_float(rg[j * 4 + 3]);
                    if (mode == 1) {
                        float4 old = *(float4*)&outp[j * 4];
                        const float4 bv = *(const float4*)&bias[col0 + cb * 32 + j * 4];
                        v.x += old.x + bv.x; v.y += old.y + bv.y;
                        v.z += old.z + bv.z; v.w += old.w + bv.w;
                    }
                    *(float4*)&outp[j * 4] = v;
                }
            }
        }
    }
    TC_FENCE_BEFORE();
    __syncthreads();
    if (tid == 0) {
#pragma unroll
        for (int s = 0; s < NSTAGE; s++) MBAR_INVAL(sbase + 8 + s * 8);
    }
    if (wid == 0) TC_DEALLOC(tmem, 128);
}

#else  /* !HAS_TCGEN05: compile-only fallback for the non-'a' PTX pass */

__device__ __forceinline__ void gemm_tc(const float* __restrict__ A,
                                        const float* __restrict__ Bt,
                                        float* __restrict__ C,
                                        const float* __restrict__ bias,
                                        int mode) {
    const int tid = threadIdx.x;
    const int row0 = blockIdx.x * BM, col0 = blockIdx.y * BN;
    const int r = row0 + (tid >> 1);
    const int c0 = col0 + (tid & 1) * 64;
    if (r >= ROWS) return;
    for (int cc = 0; cc < 64; cc++) {
        int c = c0 + cc;
        float s = 0.f;
        for (int k = 0; k < DIM; k++) s += A[(size_t)r * DIM + k] * Bt[(size_t)c * DIM + k];
        size_t o = (size_t)r * DIM + c;
        if (mode == 0) C[o] = s;
        else           C[o] += s + bias[c];
    }
}
#endif  /* HAS_TCGEN05 */

__global__ void k_gemm_qkv(const float* __restrict__ X, int layer) {
    const float* Bt; float* C;
    const float* base = g_Wt + (size_t)layer * 4 * DIM * DIM;
    if (blockIdx.z == 0)      { Bt = base;                 C = g_Q; }
    else if (blockIdx.z == 1) { Bt = base + DIM * DIM;     C = g_K; }
    else                      { Bt = base + 2 * DIM * DIM; C = g_V; }
    gemm_tc(X, Bt, C, nullptr, 0);
}

__global__ void k_gemm_resid(int layer, const float* __restrict__ bo,
                             float* __restrict__ X) {
    const float* Bt = g_Wt + ((size_t)layer * 4 + 3) * DIM * DIM;
    gemm_tc(g_A, Bt, X, bo, 1);
}

// ---------------- Axial attention: parallel softmax (64-lane reduce) ----------
__global__ void k_axial(int typ) {
    const int n = blockIdx.x;
    const int head = blockIdx.y;
    const int b = blockIdx.z;
    __shared__ float Ks[49][65];
    __shared__ float Vs[49][65];
    __shared__ float Qs[2][64];
    __shared__ float sc[2][64];
    __shared__ float rmax[2][2];
    __shared__ float rsum[2][2];
    const int tid = threadIdx.x;

    for (int idx = tid; idx < 49 * 64; idx += 128) {
        int j = idx >> 6, d = idx & 63;
        int pos = (j == 0) ? 0 : (typ == 0 ? 1 + n * GWID + (j - 1)
                                           : 1 + (j - 1) * GWID + n);
        size_t o = ((size_t)(b * SEQ + pos)) * DIM + head * DHEAD + d;
        Ks[j][d] = g_K[o];
        Vs[j][d] = g_V[o];
    }
    __syncthreads();

    const int sub = tid >> 6;       // 0/1 : two queries in flight
    const int l = tid & 63;
    const int w = (tid >> 5) & 1;   // warp within sub
    for (int q0 = 0; q0 < 49; q0 += 2) {
        int qi = q0 + sub;
        bool act = (qi < 49);
        int qpos = 0;
        if (act) {
            qpos = (qi == 0) ? 0 : (typ == 0 ? 1 + n * GWID + (qi - 1)
                                             : 1 + (qi - 1) * GWID + n);
            Qs[sub][l] = g_Q[((size_t)(b * SEQ + qpos)) * DIM + head * DHEAD + l];
        }
        __syncthreads();
        float s = -FLT_MAX;
        if (act && l <= qi) {
            float acc = 0.f;
#pragma unroll 16
            for (int d = 0; d < 64; d++) acc += Qs[sub][d] * Ks[l][d];
            s = acc * 0.125f;
        }
        // 64-lane max reduce
        float m = s;
        for (int off = 16; off; off >>= 1) m = fmaxf(m, __shfl_xor_sync(0xffffffffu, m, off));
        if ((tid & 31) == 0) rmax[sub][w] = m;
        __syncthreads();
        m = fmaxf(rmax[sub][0], rmax[sub][1]);
        float pv = (act && l <= qi) ? expf(s - m) : 0.0f;
        float su = pv;
        for (int off = 16; off; off >>= 1) su += __shfl_xor_sync(0xffffffffu, su, off);
        if ((tid & 31) == 0) rsum[sub][w] = su;
        __syncthreads();
        su = rsum[sub][0] + rsum[sub][1];
        sc[sub][l] = pv / su;
        __syncthreads();
        if (act && !(qi == 0 && n != 0)) {
            float o = 0.f;
            for (int j = 0; j <= qi; j++) o += sc[sub][j] * Vs[j][l];
            g_A[((size_t)(b * SEQ + qpos)) * DIM + head * DHEAD + l] = o;
        }
        __syncthreads();
    }
}

// ---------------- Nearby attention, tiled: CTA = (b, head, t, 2-row h-band) ----
#define KSTRIDE 65
#define NB_KOFF 0
#define NB_VOFF (384*KSTRIDE)
#define NB_QOFF (2*384*KSTRIDE)
#define NB_POFF (NB_QOFF + 8*64)
#define NB_ROFF (NB_POFF + 8*128)
#define NB_SMEM_FLOATS (NB_ROFF + 8*128)
#define NB_SMEM_BYTES (NB_SMEM_FLOATS*4)   /* 209920 */

__global__ void k_nearby_t() {
    extern __shared__ float sm[];
    const int tid = threadIdx.x;
    const int wid = tid >> 5;
    const int lane = tid & 31;
    const int t = blockIdx.y;
    const int h0 = blockIdx.x * 2;
    const int b = blockIdx.z >> 3;
    const int head = blockIdx.z & 7;
    const size_t base = ((size_t)b * SEQ) * DIM + head * DHEAD;
    const int t0 = max(0, t - 3);
    const int nf = t - t0 + 1;

    const int nchunks = nf * 96 * 16;
    for (int idx = tid; idx < nchunks; idx += 256) {
        const int row = idx >> 4, c4 = idx & 15;
        const int f = row / 96, rem = row % 96;
        const int hloc = rem >> 4, wk = rem & 15;
        const int hk = h0 - 2 + hloc;
        if (hk >= 0 && hk < 16) {
            const int kp = 1 + (t0 + f) * 256 + hk * 16 + wk;
            const size_t go = base + (size_t)kp * DIM + c4 * 4;
            float4 kv = *(const float4*)&g_K[go];
            float4 vv = *(const float4*)&g_V[go];
            float* kd = &sm[NB_KOFF + row * KSTRIDE + c4 * 4];
            float* vd = &sm[NB_VOFF + row * KSTRIDE + c4 * 4];
            kd[0] = kv.x; kd[1] = kv.y; kd[2] = kv.z; kd[3] = kv.w;
            vd[0] = vv.x; vd[1] = vv.y; vd[2] = vv.z; vd[3] = vv.w;
        }
    }
    __syncthreads();

    float* qsh = &sm[NB_QOFF + wid * 64];
    float* psh = &sm[NB_POFF + wid * 128];
    int*   rsh = (int*)&sm[NB_ROFF + wid * 128];

    for (int j = 0; j < 4; j++) {
        const int q = wid + 8 * j;
        const int qh_off = q >> 4, qw = q & 15;
        const int h = h0 + qh_off;
        const int i = t * 256 + h * 16 + qw;

        if (i == 0) {
            float* out0 = &g_A[base];
            out0[lane]      = g_V[base + lane];
            out0[lane + 32] = g_V[base + lane + 32];
            float a0 = 0.f, a1 = 0.f;
            for (int r = 0; r < SEQ; r++) {
                a0 += g_V[base + (size_t)r * DIM + lane];
                a1 += g_V[base + (size_t)r * DIM + lane + 32];
            }
            const float inv = 1.0f / (float)SEQ;
            float* outU = &g_A[base + (size_t)S_IMG * DIM];
            outU[lane]      = a0 * inv;
            outU[lane + 32] = a1 * inv;
            continue;
        }
        const int p = i;
        qsh[lane]      = g_Q[base + (size_t)p * DIM + lane];
        qsh[lane + 32] = g_Q[base + (size_t)p * DIM + lane + 32];
        __syncwarp();

        const int nslots = nf * 25;
        float sloc[4]; int myrow[4];
#pragma unroll
        for (int s = 0; s < 4; s++) {
            const int slot = lane + 32 * s;
            float scv = -FLT_MAX; int r = -1;
            if (slot < nslots) {
                const int f = slot / 25, rr = slot % 25;
                const int dh = rr / 5, dw = rr % 5;
                const int tk = t0 + f;
                const int hk = h - 2 + dh, wk = qw - 2 + dw;
                if (hk >= 0 && hk < 16 && wk >= 0 && wk < 16 &&
                    (tk < t || rr < 12)) {
                    r = f * 96 + (qh_off + dh) * 16 + wk;
                    const float* kr = &sm[NB_KOFF + r * KSTRIDE];
                    float acc = 0.f;
#pragma unroll 16
                    for (int d = 0; d < 64; d++) acc += qsh[d] * kr[d];
                    scv = acc * 0.125f;
                }
            }
            sloc[s] = scv; myrow[s] = r;
            if (slot < 128) rsh[slot] = r;
        }
        float m = fmaxf(fmaxf(sloc[0], sloc[1]), fmaxf(sloc[2], sloc[3]));
        for (int off = 16; off; off >>= 1) m = fmaxf(m, __shfl_xor_sync(0xffffffffu, m, off));
        float sum = 0.f;
#pragma unroll
        for (int s = 0; s < 4; s++) {
            const int slot = lane + 32 * s;
            float pv = (myrow[s] >= 0) ? expf(sloc[s] - m) : 0.0f;
            if (slot < 128) psh[slot] = pv;
            sum += pv;
        }
        for (int off = 16; off; off >>= 1) sum += __shfl_xor_sync(0xffffffffu, sum, off);
        const float inv = 1.0f / sum;
        __syncwarp();

        float o0 = 0.f, o1 = 0.f;
        for (int slot = 0; slot < nslots; slot++) {
            const int r = rsh[slot];
            if (r < 0) continue;
            const float pv = psh[slot];
            const float* vr = &sm[NB_VOFF + r * KSTRIDE];
            o0 += pv * vr[lane];
            o1 += pv * vr[lane + 32];
        }
        g_A[base + (size_t)p * DIM + lane]      = o0 * inv;
        g_A[base + (size_t)p * DIM + lane + 32] = o1 * inv;
        __syncwarp();
    }
}

// ---------------- driver ----------------
extern "C" void kernel_launch(void* const* d_in, const int* in_sizes, int n_in,
                              void* d_out, int out_size) {
    const float* x = (const float*)d_in[0];
    float* X = (float*)d_out;

    static int configured = 0;
    if (!configured) {
        cudaFuncSetAttribute(k_gemm_qkv, cudaFuncAttributeMaxDynamicSharedMemorySize, SMEM_TOTAL);
        cudaFuncSetAttribute(k_gemm_resid, cudaFuncAttributeMaxDynamicSharedMemorySize, SMEM_TOTAL);
        cudaFuncSetAttribute(k_nearby_t, cudaFuncAttributeMaxDynamicSharedMemorySize, NB_SMEM_BYTES);
        configured = 1;
    }

    cudaMemcpyAsync(X, x, sizeof(float) * (size_t)ROWS * DIM,
                    cudaMemcpyDeviceToDevice, 0);

    k_transpose<<<dim3(16, 16, 12), dim3(32, 8)>>>(
        (const float*)d_in[2],  (const float*)d_in[3],  (const float*)d_in[4],  (const float*)d_in[5],
        (const float*)d_in[7],  (const float*)d_in[8],  (const float*)d_in[9],  (const float*)d_in[10],
        (const float*)d_in[12], (const float*)d_in[13], (const float*)d_in[14], (const float*)d_in[15]);

    dim3 gq((ROWS + BM - 1) / BM, DIM / BN, 3);   // 37 x 4 x 3
    dim3 go((ROWS + BM - 1) / BM, DIM / BN, 1);   // 37 x 4
    for (int l = 0; l < 3; l++) {
        const float* bo = (const float*)d_in[2 + l * 5 + 4];
        k_gemm_qkv<<<gq, 256, SMEM_TOTAL>>>(X, l);
        if (l < 2) k_axial<<<dim3(48, 8, 2), 128>>>(l);
        else       k_nearby_t<<<dim3(8, 9, 16), 256, NB_SMEM_BYTES>>>();
        k_gemm_resid<<<go, 256, SMEM_TOTAL>>>(l, bo, X);
    }
}

// round 10
// speedup vs baseline: 3.8894x; 1.0317x over previous
#include <cuda_runtime.h>
#include <math.h>
#include <float.h>
#include <stdint.h>

#define BB 2
#define SEQ 2305
#define S_IMG 2304
#define DIM 512
#define HEADS 8
#define DHEAD 64
#define ROWS (BB*SEQ)   /* 4610 */
#define GWID 48

#define BM 128
#define BN 128
#define BKC 32              /* k per smem chunk */
#define NCHUNK (DIM/BKC)    /* 16 */

// tcgen05 available only in the arch-specific ('a') compilation pass.
#if !defined(__CUDA_ARCH__) || defined(__CUDA_ARCH_FEAT_SM103_ALL) || defined(__CUDA_ARCH_FEAT_SM100_ALL) || defined(__CUDA_ARCH_FEAT_SM101_ALL)
#define HAS_TCGEN05 1
#else
#define HAS_TCGEN05 0
#endif

__device__ float g_Q[ROWS*DIM];
__device__ float g_K[ROWS*DIM];
__device__ float g_V[ROWS*DIM];
__device__ float g_A[ROWS*DIM];
__device__ float g_Wt[12*DIM*DIM];   /* transposed weights [n][k] */

// SMEM header: [0:4) tmem ptr, [8:136) 16 full mbars, [136:264) 16 mma mbars
#define SMEM_TILE0 1024
#define SMEM_Q_TOTAL (1024 + 3*3*16384 + 3*16384)   /* NS=3, stage 64KB -> 197632 */
#define SMEM_R_TOTAL (1024 + 6*2*16384)             /* NS=6, stage 32KB -> 197632 */

__device__ __forceinline__ uint32_t sw128(uint32_t off) {
    return off ^ ((off >> 3) & 0x70);
}

// ---------------- weight transpose: g_Wt[m][n][k] = W_m[k][n] ----------------
__global__ void k_transpose(const float* w0, const float* w1, const float* w2,
                            const float* w3, const float* w4, const float* w5,
                            const float* w6, const float* w7, const float* w8,
                            const float* w9, const float* w10, const float* w11) {
    const float* ws[12] = {w0,w1,w2,w3,w4,w5,w6,w7,w8,w9,w10,w11};
    const float* W = ws[blockIdx.z];
    float* out = g_Wt + (size_t)blockIdx.z * DIM * DIM;
    __shared__ float t[32][33];
    const int nx = blockIdx.x * 32, ky = blockIdx.y * 32;
#pragma unroll
    for (int j = 0; j < 4; j++) {
        int k = ky + threadIdx.y + j * 8;
        t[threadIdx.y + j * 8][threadIdx.x] = W[(size_t)k * DIM + nx + threadIdx.x];
    }
    __syncthreads();
#pragma unroll
    for (int j = 0; j < 4; j++) {
        int n = nx + threadIdx.y + j * 8;
        out[(size_t)n * DIM + ky + threadIdx.x] = t[threadIdx.x][threadIdx.y + j * 8];
    }
}

#if HAS_TCGEN05
// ---------------- tcgen05 helpers ----------------
__device__ __forceinline__ uint32_t smem_u32(const void* p) {
    uint32_t a;
    asm("{ .reg .u64 t; cvta.to.shared.u64 t, %1; cvt.u32.u64 %0, t; }" : "=r"(a) : "l"(p));
    return a;
}
__device__ __forceinline__ uint32_t elect_one() {
    uint32_t p;
    asm volatile("{ .reg .pred p; elect.sync _|p, 0xFFFFFFFF; selp.b32 %0,1,0,p; }" : "=r"(p));
    return p;
}
static __device__ __forceinline__ uint64_t make_desc(uint32_t addr) {
    const uint64_t base = (uint64_t(2) << 61) | (uint64_t(1) << 46) |
                          (uint64_t(64) << 32) | (uint64_t(1) << 16);
    return base | ((uint64_t)(addr >> 4) & 0x3FFF);
}
#define IDESC_TF32 ((1u<<4) | (2u<<7) | (2u<<10) | ((BN/8u)<<17) | ((BM/16u)<<24))

__device__ __forceinline__ void mma_tf32(uint32_t d_tmem, uint64_t a_desc,
                                         uint64_t b_desc, uint32_t en) {
    asm volatile(
        "{\n\t.reg .pred p;\n\t"
        "setp.ne.u32 p, %4, 0;\n\t"
        "tcgen05.mma.cta_group::1.kind::tf32 [%0], %1, %2, %3, {%5,%5,%5,%5}, p;\n\t}"
        :: "r"(d_tmem), "l"(a_desc), "l"(b_desc), "r"(IDESC_TF32), "r"(en), "r"(0u)
        : "memory");
}
#define MBAR_INIT(a,c)  asm volatile("mbarrier.init.shared.b64 [%0], %1;" :: "r"(a), "r"(c) : "memory")
#define COMMIT_CG1(a)   asm volatile("tcgen05.commit.cta_group::1.mbarrier::arrive::one.shared::cluster.b64 [%0];" :: "r"(a) : "memory")
__device__ __forceinline__ void mbar_wait(uint32_t addr, uint32_t parity) {
    asm volatile(
        "{\n\t.reg .pred P1;\n\t"
        "WL_%=:\n\t"
        "mbarrier.try_wait.parity.acquire.cta.shared::cta.b64 P1, [%0], %1, 0x989680;\n\t"
        "@P1 bra.uni WD_%=;\n\t"
        "bra.uni WL_%=;\n\t"
        "WD_%=:\n\t}"
        :: "r"(addr), "r"(parity) : "memory");
}
#define FENCE_ASYNC()   asm volatile("fence.proxy.async.shared::cta;" ::: "memory")
#define TC_ALLOC(sp,n)  asm volatile("tcgen05.alloc.cta_group::1.sync.aligned.shared::cta.b32 [%0], %1;" :: "r"(sp), "r"(n) : "memory")
#define TC_DEALLOC(t,n) asm volatile("tcgen05.dealloc.cta_group::1.sync.aligned.b32 %0, %1;" :: "r"(t), "r"(n))
#define TC_FENCE_AFTER()  asm volatile("tcgen05.fence::after_thread_sync;" ::: "memory")
#define TC_FENCE_BEFORE() asm volatile("tcgen05.fence::before_thread_sync;" ::: "memory")
#define TC_WAIT_LD()      asm volatile("tcgen05.wait::ld.sync.aligned;" ::: "memory")
#define LDTM_X32(r, a) \
    asm volatile("tcgen05.ld.sync.aligned.32x32b.x32.b32 " \
        "{%0,%1,%2,%3,%4,%5,%6,%7,%8,%9,%10,%11,%12,%13,%14,%15," \
        "%16,%17,%18,%19,%20,%21,%22,%23,%24,%25,%26,%27,%28,%29,%30,%31}, [%32];" \
        : "=r"((r)[0]),"=r"((r)[1]),"=r"((r)[2]),"=r"((r)[3]),"=r"((r)[4]),"=r"((r)[5]),"=r"((r)[6]),"=r"((r)[7]), \
          "=r"((r)[8]),"=r"((r)[9]),"=r"((r)[10]),"=r"((r)[11]),"=r"((r)[12]),"=r"((r)[13]),"=r"((r)[14]),"=r"((r)[15]), \
          "=r"((r)[16]),"=r"((r)[17]),"=r"((r)[18]),"=r"((r)[19]),"=r"((r)[20]),"=r"((r)[21]),"=r"((r)[22]),"=r"((r)[23]), \
          "=r"((r)[24]),"=r"((r)[25]),"=r"((r)[26]),"=r"((r)[27]),"=r"((r)[28]),"=r"((r)[29]),"=r"((r)[30]),"=r"((r)[31]) \
        : "r"(a))
#define CP_A16(d,s) asm volatile("cp.async.cg.shared.global [%0], [%1], 16;" :: "r"(d), "l"(s) : "memory")
#define CP_ARRIVE(m) asm volatile("cp.async.mbarrier.arrive.noinc.shared::cta.b64 [%0];" :: "r"(m) : "memory")

// Load one stage: A chunk 128x32 + NMAT B chunks 128x32 (all K-contiguous).
template<int NMAT>
__device__ __forceinline__ void load_stage2(const float* __restrict__ A,
                                            const float* __restrict__ BtBase,
                                            int row0, int col0, int kbase,
                                            uint32_t sb32, int arow, int aseg) {
#pragma unroll
    for (int u = 0; u < 4; u++) {
        const int row = arow + 32 * u;
        const uint32_t off = sw128((uint32_t)(row * 128 + aseg * 16));
        const int gr = row0 + row;
        if (gr < ROWS)
            CP_A16(sb32 + off, &A[(size_t)gr * DIM + kbase + aseg * 4]);
#pragma unroll
        for (int m = 0; m < NMAT; m++)
            CP_A16(sb32 + 16384 * (1 + m) + off,
                   &BtBase[(size_t)m * DIM * DIM + (size_t)(col0 + row) * DIM + kbase + aseg * 4]);
    }
}

// ---------------- tcgen05 tf32 GEMM, barrier-free mbarrier pipeline ----------
// One-shot mbarriers per chunk: full[c] (256 arrivals via cp.async), mma[c] (commit).
template<int NS, int NMAT>
__device__ __forceinline__ void gemm_tc2(const float* __restrict__ A,
                                         const float* __restrict__ BtBase,
                                         float* __restrict__ C0,
                                         float* __restrict__ C1,
                                         float* __restrict__ C2,
                                         const float* __restrict__ bias,
                                         int mode) {
    extern __shared__ char smem[];
    const int tid = threadIdx.x;
    const int wid = tid >> 5;
    const int lane = tid & 31;
    const int row0 = blockIdx.x * BM, col0 = blockIdx.y * BN;
    const uint32_t sbase = smem_u32(smem);
    const int arow = tid >> 3, aseg = tid & 7;
    const int STG = 16384 * (1 + NMAT);
    const int ACOLS = (NMAT == 1) ? 128 : 512;

    if (wid == 0) TC_ALLOC(sbase, ACOLS);
    if (tid < 16)       MBAR_INIT(sbase + 8 + tid * 8, 256);          // full[c]
    else if (tid < 32)  MBAR_INIT(sbase + 136 + (tid - 16) * 8, 1);   // mma[c]

    // pre-zero A regions of all stages if this row-tile has OOB rows
    if (row0 + BM > ROWS) {
        for (int i = tid; i < NS * 1024; i += 256)   /* NS stages x 16KB / 16B */
            *(float4*)(smem + SMEM_TILE0 + (i / 1024) * STG + (i % 1024) * 16)
                = make_float4(0.f, 0.f, 0.f, 0.f);
        FENCE_ASYNC();
    }
    __syncthreads();
    uint32_t tmem;
    asm volatile("ld.shared.b32 %0, [%1];" : "=r"(tmem) : "r"(sbase));

    // prologue: stages 0..NS-2
#pragma unroll
    for (int s = 0; s < NS - 1; s++) {
        load_stage2<NMAT>(A, BtBase, row0, col0, s * BKC,
                          sbase + SMEM_TILE0 + s * STG, arow, aseg);
        CP_ARRIVE(sbase + 8 + s * 8);
    }

    for (int c = 0; c < NCHUNK; c++) {
        if (wid == 0) {
            if (elect_one()) {
                mbar_wait(sbase + 8 + c * 8, 0);       // full[c]
                FENCE_ASYNC();
                const uint32_t st = sbase + SMEM_TILE0 + (c % NS) * STG;
                uint64_t ad = make_desc(st);
#pragma unroll
                for (int m = 0; m < NMAT; m++) {
                    uint64_t bd = make_desc(st + 16384 * (1 + m));
#pragma unroll
                    for (int s4 = 0; s4 < 4; s4++)
                        mma_tf32(tmem + m * 128, ad + s4 * 2, bd + s4 * 2,
                                 (uint32_t)(c * 4 + s4 > 0));
                }
                COMMIT_CG1(sbase + 136 + c * 8);       // mma[c]
            }
        }
        const int s = c + NS - 1;
        if (s < NCHUNK) {
            if (s >= NS) mbar_wait(sbase + 136 + (s - NS) * 8, 0);  // buffer free
            load_stage2<NMAT>(A, BtBase, row0, col0, s * BKC,
                              sbase + SMEM_TILE0 + (s % NS) * STG, arow, aseg);
            CP_ARRIVE(sbase + 8 + s * 8);
        }
    }
    mbar_wait(sbase + 136 + (NCHUNK - 1) * 8, 0);       // all MMAs done

    TC_FENCE_AFTER();
    float* Cs[3] = {C0, C1, C2};
    if (wid < 4) {
        const int r = row0 + wid * 32 + lane;
#pragma unroll
        for (int m = 0; m < NMAT; m++) {
            float* C = Cs[m];
#pragma unroll
            for (int cb = 0; cb < 4; cb++) {
                uint32_t rg[32];
                LDTM_X32(rg, tmem + m * 128 + cb * 32);
                TC_WAIT_LD();
                if (r < ROWS) {
                    float* outp = &C[(size_t)r * DIM + col0 + cb * 32];
#pragma unroll
                    for (int j = 0; j < 8; j++) {
                        float4 v;
                        v.x = __uint_as_float(rg[j * 4 + 0]);
                        v.y = __uint_as_float(rg[j * 4 + 1]);
                        v.z = __uint_as_float(rg[j * 4 + 2]);
                        v.w = __uint_as_float(rg[j * 4 + 3]);
                        if (mode == 1) {
                            float4 old = *(float4*)&outp[j * 4];
                            const float4 bv = *(const float4*)&bias[col0 + cb * 32 + j * 4];
                            v.x += old.x + bv.x; v.y += old.y + bv.y;
                            v.z += old.z + bv.z; v.w += old.w + bv.w;
                        }
                        *(float4*)&outp[j * 4] = v;
                    }
                }
            }
        }
    }
    TC_FENCE_BEFORE();
    __syncthreads();
    if (wid == 0) TC_DEALLOC(tmem, ACOLS);
}

#else  /* !HAS_TCGEN05: compile-only fallback for the non-'a' PTX pass */

template<int NS, int NMAT>
__device__ __forceinline__ void gemm_tc2(const float* __restrict__ A,
                                         const float* __restrict__ BtBase,
                                         float* __restrict__ C0,
                                         float* __restrict__ C1,
                                         float* __restrict__ C2,
                                         const float* __restrict__ bias,
                                         int mode) {
    const int tid = threadIdx.x;
    const int row0 = blockIdx.x * BM, col0 = blockIdx.y * BN;
    const int r = row0 + (tid >> 1);
    const int c0 = col0 + (tid & 1) * 64;
    if (r >= ROWS) return;
    float* Cs[3] = {C0, C1, C2};
    for (int m = 0; m < NMAT; m++) {
        const float* Bt = BtBase + (size_t)m * DIM * DIM;
        for (int cc = 0; cc < 64; cc++) {
            int c = c0 + cc;
            float s = 0.f;
            for (int k = 0; k < DIM; k++) s += A[(size_t)r * DIM + k] * Bt[(size_t)c * DIM + k];
            size_t o = (size_t)r * DIM + c;
            if (mode == 0) Cs[m][o] = s;
            else           Cs[m][o] += s + bias[c];
        }
    }
}
#endif  /* HAS_TCGEN05 */

__global__ void k_gemm_qkv(const float* __restrict__ X, int layer) {
    const float* base = g_Wt + (size_t)layer * 4 * DIM * DIM;   // Wq,Wk,Wv contiguous
    gemm_tc2<3, 3>(X, base, g_Q, g_K, g_V, nullptr, 0);
}

__global__ void k_gemm_resid(int layer, const float* __restrict__ bo,
                             float* __restrict__ X) {
    const float* Bt = g_Wt + ((size_t)layer * 4 + 3) * DIM * DIM;
    gemm_tc2<6, 1>(g_A, Bt, X, nullptr, nullptr, bo, 1);
}

// ---------------- Axial attention: parallel softmax (64-lane reduce) ----------
__global__ void k_axial(int typ) {
    const int n = blockIdx.x;
    const int head = blockIdx.y;
    const int b = blockIdx.z;
    __shared__ float Ks[49][65];
    __shared__ float Vs[49][65];
    __shared__ float Qs[2][64];
    __shared__ float sc[2][64];
    __shared__ float rmax[2][2];
    __shared__ float rsum[2][2];
    const int tid = threadIdx.x;

    for (int idx = tid; idx < 49 * 64; idx += 128) {
        int j = idx >> 6, d = idx & 63;
        int pos = (j == 0) ? 0 : (typ == 0 ? 1 + n * GWID + (j - 1)
                                           : 1 + (j - 1) * GWID + n);
        size_t o = ((size_t)(b * SEQ + pos)) * DIM + head * DHEAD + d;
        Ks[j][d] = g_K[o];
        Vs[j][d] = g_V[o];
    }
    __syncthreads();

    const int sub = tid >> 6;
    const int l = tid & 63;
    const int w = (tid >> 5) & 1;
    for (int q0 = 0; q0 < 49; q0 += 2) {
        int qi = q0 + sub;
        bool act = (qi < 49);
        int qpos = 0;
        if (act) {
            qpos = (qi == 0) ? 0 : (typ == 0 ? 1 + n * GWID + (qi - 1)
                                             : 1 + (qi - 1) * GWID + n);
            Qs[sub][l] = g_Q[((size_t)(b * SEQ + qpos)) * DIM + head * DHEAD + l];
        }
        __syncthreads();
        float s = -FLT_MAX;
        if (act && l <= qi) {
            float acc = 0.f;
#pragma unroll 16
            for (int d = 0; d < 64; d++) acc += Qs[sub][d] * Ks[l][d];
            s = acc * 0.125f;
        }
        float m = s;
        for (int off = 16; off; off >>= 1) m = fmaxf(m, __shfl_xor_sync(0xffffffffu, m, off));
        if ((tid & 31) == 0) rmax[sub][w] = m;
        __syncthreads();
        m = fmaxf(rmax[sub][0], rmax[sub][1]);
        float pv = (act && l <= qi) ? expf(s - m) : 0.0f;
        float su = pv;
        for (int off = 16; off; off >>= 1) su += __shfl_xor_sync(0xffffffffu, su, off);
        if ((tid & 31) == 0) rsum[sub][w] = su;
        __syncthreads();
        su = rsum[sub][0] + rsum[sub][1];
        sc[sub][l] = pv / su;
        __syncthreads();
        if (act && !(qi == 0 && n != 0)) {
            float o = 0.f;
            for (int j = 0; j <= qi; j++) o += sc[sub][j] * Vs[j][l];
            g_A[((size_t)(b * SEQ + qpos)) * DIM + head * DHEAD + l] = o;
        }
        __syncthreads();
    }
}

// ---------------- Nearby attention, tiled: CTA = (b, head, t, 2-row h-band) ----
#define KSTRIDE 65
#define NB_KOFF 0
#define NB_VOFF (384*KSTRIDE)
#define NB_QOFF (2*384*KSTRIDE)
#define NB_POFF (NB_QOFF + 8*64)
#define NB_ROFF (NB_POFF + 8*128)
#define NB_SMEM_FLOATS (NB_ROFF + 8*128)
#define NB_SMEM_BYTES (NB_SMEM_FLOATS*4)   /* 209920 */

__global__ void k_nearby_t() {
    extern __shared__ float sm[];
    const int tid = threadIdx.x;
    const int wid = tid >> 5;
    const int lane = tid & 31;
    const int t = blockIdx.y;
    const int h0 = blockIdx.x * 2;
    const int b = blockIdx.z >> 3;
    const int head = blockIdx.z & 7;
    const size_t base = ((size_t)b * SEQ) * DIM + head * DHEAD;
    const int t0 = max(0, t - 3);
    const int nf = t - t0 + 1;

    const int nchunks = nf * 96 * 16;
    for (int idx = tid; idx < nchunks; idx += 256) {
        const int row = idx >> 4, c4 = idx & 15;
        const int f = row / 96, rem = row % 96;
        const int hloc = rem >> 4, wk = rem & 15;
        const int hk = h0 - 2 + hloc;
        if (hk >= 0 && hk < 16) {
            const int kp = 1 + (t0 + f) * 256 + hk * 16 + wk;
            const size_t go = base + (size_t)kp * DIM + c4 * 4;
            float4 kv = *(const float4*)&g_K[go];
            float4 vv = *(const float4*)&g_V[go];
            float* kd = &sm[NB_KOFF + row * KSTRIDE + c4 * 4];
            float* vd = &sm[NB_VOFF + row * KSTRIDE + c4 * 4];
            kd[0] = kv.x; kd[1] = kv.y; kd[2] = kv.z; kd[3] = kv.w;
            vd[0] = vv.x; vd[1] = vv.y; vd[2] = vv.z; vd[3] = vv.w;
        }
    }
    __syncthreads();

    float* qsh = &sm[NB_QOFF + wid * 64];
    float* psh = &sm[NB_POFF + wid * 128];
    int*   rsh = (int*)&sm[NB_ROFF + wid * 128];

    for (int j = 0; j < 4; j++) {
        const int q = wid + 8 * j;
        const int qh_off = q >> 4, qw = q & 15;
        const int h = h0 + qh_off;
        const int i = t * 256 + h * 16 + qw;

        if (i == 0) {
            float* out0 = &g_A[base];
            out0[lane]      = g_V[base + lane];
            out0[lane + 32] = g_V[base + lane + 32];
            float a0 = 0.f, a1 = 0.f;
            for (int r = 0; r < SEQ; r++) {
                a0 += g_V[base + (size_t)r * DIM + lane];
                a1 += g_V[base + (size_t)r * DIM + lane + 32];
            }
            const float inv = 1.0f / (float)SEQ;
            float* outU = &g_A[base + (size_t)S_IMG * DIM];
            outU[lane]      = a0 * inv;
            outU[lane + 32] = a1 * inv;
            continue;
        }
        const int p = i;
        qsh[lane]      = g_Q[base + (size_t)p * DIM + lane];
        qsh[lane + 32] = g_Q[base + (size_t)p * DIM + lane + 32];
        __syncwarp();

        const int nslots = nf * 25;
        float sloc[4]; int myrow[4];
#pragma unroll
        for (int s = 0; s < 4; s++) {
            const int slot = lane + 32 * s;
            float scv = -FLT_MAX; int r = -1;
            if (slot < nslots) {
                const int f = slot / 25, rr = slot % 25;
                const int dh = rr / 5, dw = rr % 5;
                const int tk = t0 + f;
                const int hk = h - 2 + dh, wk = qw - 2 + dw;
                if (hk >= 0 && hk < 16 && wk >= 0 && wk < 16 &&
                    (tk < t || rr < 12)) {
                    r = f * 96 + (qh_off + dh) * 16 + wk;
                    const float* kr = &sm[NB_KOFF + r * KSTRIDE];
                    float acc = 0.f;
#pragma unroll 16
                    for (int d = 0; d < 64; d++) acc += qsh[d] * kr[d];
                    scv = acc * 0.125f;
                }
            }
            sloc[s] = scv; myrow[s] = r;
            if (slot < 128) rsh[slot] = r;
        }
        float m = fmaxf(fmaxf(sloc[0], sloc[1]), fmaxf(sloc[2], sloc[3]));
        for (int off = 16; off; off >>= 1) m = fmaxf(m, __shfl_xor_sync(0xffffffffu, m, off));
        float sum = 0.f;
#pragma unroll
        for (int s = 0; s < 4; s++) {
            const int slot = lane + 32 * s;
            float pv = (myrow[s] >= 0) ? expf(sloc[s] - m) : 0.0f;
            if (slot < 128) psh[slot] = pv;
            sum += pv;
        }
        for (int off = 16; off; off >>= 1) sum += __shfl_xor_sync(0xffffffffu, sum, off);
        const float inv = 1.0f / sum;
        __syncwarp();

        float o0 = 0.f, o1 = 0.f;
        for (int slot = 0; slot < nslots; slot++) {
            const int r = rsh[slot];
            if (r < 0) continue;
            const float pv = psh[slot];
            const float* vr = &sm[NB_VOFF + r * KSTRIDE];
            o0 += pv * vr[lane];
            o1 += pv * vr[lane + 32];
        }
        g_A[base + (size_t)p * DIM + lane]      = o0 * inv;
        g_A[base + (size_t)p * DIM + lane + 32] = o1 * inv;
        __syncwarp();
    }
}

// ---------------- driver ----------------
extern "C" void kernel_launch(void* const* d_in, const int* in_sizes, int n_in,
                              void* d_out, int out_size) {
    const float* x = (const float*)d_in[0];
    float* X = (float*)d_out;

    static int configured = 0;
    if (!configured) {
        cudaFuncSetAttribute(k_gemm_qkv, cudaFuncAttributeMaxDynamicSharedMemorySize, SMEM_Q_TOTAL);
        cudaFuncSetAttribute(k_gemm_resid, cudaFuncAttributeMaxDynamicSharedMemorySize, SMEM_R_TOTAL);
        cudaFuncSetAttribute(k_nearby_t, cudaFuncAttributeMaxDynamicSharedMemorySize, NB_SMEM_BYTES);
        configured = 1;
    }

    cudaMemcpyAsync(X, x, sizeof(float) * (size_t)ROWS * DIM,
                    cudaMemcpyDeviceToDevice, 0);

    k_transpose<<<dim3(16, 16, 12), dim3(32, 8)>>>(
        (const float*)d_in[2],  (const float*)d_in[3],  (const float*)d_in[4],  (const float*)d_in[5],
        (const float*)d_in[7],  (const float*)d_in[8],  (const float*)d_in[9],  (const float*)d_in[10],
        (const float*)d_in[12], (const float*)d_in[13], (const float*)d_in[14], (const float*)d_in[15]);

    dim3 gg((ROWS + BM - 1) / BM, DIM / BN);   // 37 x 4 = 148 CTAs
    for (int l = 0; l < 3; l++) {
        const float* bo = (const float*)d_in[2 + l * 5 + 4];
        k_gemm_qkv<<<gg, 256, SMEM_Q_TOTAL>>>(X, l);
        if (l < 2) k_axial<<<dim3(48, 8, 2), 128>>>(l);
        else       k_nearby_t<<<dim3(8, 9, 16), 256, NB_SMEM_BYTES>>>();
        k_gemm_resid<<<gg, 256, SMEM_R_TOTAL>>>(l, bo, X);
    }
}

// round 11
// speedup vs baseline: 4.3933x; 1.1296x over previous
#include <cuda_runtime.h>
#include <cuda.h>
#include <math.h>
#include <float.h>
#include <stdint.h>

#define BB 2
#define SEQ 2305
#define S_IMG 2304
#define DIM 512
#define HEADS 8
#define DHEAD 64
#define ROWS (BB*SEQ)   /* 4610 */
#define GWID 48

#define BM 128
#define BN 128
#define BKC 32              /* k per smem chunk */
#define NCHUNK (DIM/BKC)    /* 16 */

// tcgen05 available only in the arch-specific ('a') compilation pass.
#if !defined(__CUDA_ARCH__) || defined(__CUDA_ARCH_FEAT_SM103_ALL) || defined(__CUDA_ARCH_FEAT_SM100_ALL) || defined(__CUDA_ARCH_FEAT_SM101_ALL)
#define HAS_TCGEN05 1
#else
#define HAS_TCGEN05 0
#endif

__device__ __align__(1024) float g_Q[ROWS*DIM];
__device__ __align__(1024) float g_K[ROWS*DIM];
__device__ __align__(1024) float g_V[ROWS*DIM];
__device__ __align__(1024) float g_A[ROWS*DIM];
__device__ __align__(1024) float g_Wt[12*DIM*DIM];   /* transposed weights [n][k] */

// SMEM header: [0:4) tmem ptr, [8:136) 16 full mbars, [136:264) 16 mma mbars
#define SMEM_TILE0 1024
#define SMEM_Q_TOTAL (1024 + 3*4*16384)   /* NS=3, stage 64KB -> 197632 */
#define SMEM_R_TOTAL (1024 + 6*2*16384)   /* NS=6, stage 32KB -> 197632 */

__device__ __forceinline__ uint32_t sw128(uint32_t off) {
    return off ^ ((off >> 3) & 0x70);
}

// ---------------- weight transpose: g_Wt[m][n][k] = W_m[k][n] ----------------
__global__ void k_transpose(const float* w0, const float* w1, const float* w2,
                            const float* w3, const float* w4, const float* w5,
                            const float* w6, const float* w7, const float* w8,
                            const float* w9, const float* w10, const float* w11) {
    const float* ws[12] = {w0,w1,w2,w3,w4,w5,w6,w7,w8,w9,w10,w11};
    const float* W = ws[blockIdx.z];
    float* out = g_Wt + (size_t)blockIdx.z * DIM * DIM;
    __shared__ float t[32][33];
    const int nx = blockIdx.x * 32, ky = blockIdx.y * 32;
#pragma unroll
    for (int j = 0; j < 4; j++) {
        int k = ky + threadIdx.y + j * 8;
        t[threadIdx.y + j * 8][threadIdx.x] = W[(size_t)k * DIM + nx + threadIdx.x];
    }
    __syncthreads();
#pragma unroll
    for (int j = 0; j < 4; j++) {
        int n = nx + threadIdx.y + j * 8;
        out[(size_t)n * DIM + ky + threadIdx.x] = t[threadIdx.x][threadIdx.y + j * 8];
    }
}

#if HAS_TCGEN05
// ---------------- tcgen05 / TMA helpers ----------------
__device__ __forceinline__ uint32_t smem_u32(const void* p) {
    uint32_t a;
    asm("{ .reg .u64 t; cvta.to.shared.u64 t, %1; cvt.u32.u64 %0, t; }" : "=r"(a) : "l"(p));
    return a;
}
static __device__ __forceinline__ uint64_t make_desc(uint32_t addr) {
    const uint64_t base = (uint64_t(2) << 61) | (uint64_t(1) << 46) |
                          (uint64_t(64) << 32) | (uint64_t(1) << 16);
    return base | ((uint64_t)(addr >> 4) & 0x3FFF);
}
#define IDESC_TF32 ((1u<<4) | (2u<<7) | (2u<<10) | ((BN/8u)<<17) | ((BM/16u)<<24))

__device__ __forceinline__ void mma_tf32(uint32_t d_tmem, uint64_t a_desc,
                                         uint64_t b_desc, uint32_t en) {
    asm volatile(
        "{\n\t.reg .pred p;\n\t"
        "setp.ne.u32 p, %4, 0;\n\t"
        "tcgen05.mma.cta_group::1.kind::tf32 [%0], %1, %2, %3, {%5,%5,%5,%5}, p;\n\t}"
        :: "r"(d_tmem), "l"(a_desc), "l"(b_desc), "r"(IDESC_TF32), "r"(en), "r"(0u)
        : "memory");
}
#define MBAR_INIT(a,c)  asm volatile("mbarrier.init.shared.b64 [%0], %1;" :: "r"(a), "r"(c) : "memory")
#define MBAR_EXPECT(a,b) asm volatile("mbarrier.arrive.expect_tx.shared.b64 _, [%0], %1;" :: "r"(a), "r"(b) : "memory")
#define COMMIT_CG1(a)   asm volatile("tcgen05.commit.cta_group::1.mbarrier::arrive::one.shared::cluster.b64 [%0];" :: "r"(a) : "memory")
__device__ __forceinline__ void mbar_wait(uint32_t addr, uint32_t parity) {
    asm volatile(
        "{\n\t.reg .pred P1;\n\t"
        "WL_%=:\n\t"
        "mbarrier.try_wait.parity.acquire.cta.shared::cta.b64 P1, [%0], %1, 0x989680;\n\t"
        "@P1 bra.uni WD_%=;\n\t"
        "bra.uni WL_%=;\n\t"
        "WD_%=:\n\t}"
        :: "r"(addr), "r"(parity) : "memory");
}
#define FENCE_ASYNC()   asm volatile("fence.proxy.async.shared::cta;" ::: "memory")
#define TC_ALLOC(sp,n)  asm volatile("tcgen05.alloc.cta_group::1.sync.aligned.shared::cta.b32 [%0], %1;" :: "r"(sp), "r"(n) : "memory")
#define TC_DEALLOC(t,n) asm volatile("tcgen05.dealloc.cta_group::1.sync.aligned.b32 %0, %1;" :: "r"(t), "r"(n))
#define TC_FENCE_AFTER()  asm volatile("tcgen05.fence::after_thread_sync;" ::: "memory")
#define TC_FENCE_BEFORE() asm volatile("tcgen05.fence::before_thread_sync;" ::: "memory")
#define TC_WAIT_LD()      asm volatile("tcgen05.wait::ld.sync.aligned;" ::: "memory")
#define LDTM_X32(r, a) \
    asm volatile("tcgen05.ld.sync.aligned.32x32b.x32.b32 " \
        "{%0,%1,%2,%3,%4,%5,%6,%7,%8,%9,%10,%11,%12,%13,%14,%15," \
        "%16,%17,%18,%19,%20,%21,%22,%23,%24,%25,%26,%27,%28,%29,%30,%31}, [%32];" \
        : "=r"((r)[0]),"=r"((r)[1]),"=r"((r)[2]),"=r"((r)[3]),"=r"((r)[4]),"=r"((r)[5]),"=r"((r)[6]),"=r"((r)[7]), \
          "=r"((r)[8]),"=r"((r)[9]),"=r"((r)[10]),"=r"((r)[11]),"=r"((r)[12]),"=r"((r)[13]),"=r"((r)[14]),"=r"((r)[15]), \
          "=r"((r)[16]),"=r"((r)[17]),"=r"((r)[18]),"=r"((r)[19]),"=r"((r)[20]),"=r"((r)[21]),"=r"((r)[22]),"=r"((r)[23]), \
          "=r"((r)[24]),"=r"((r)[25]),"=r"((r)[26]),"=r"((r)[27]),"=r"((r)[28]),"=r"((r)[29]),"=r"((r)[30]),"=r"((r)[31]) \
        : "r"(a))
#define TMA_2D(smem, tmap, cx, cy, mbar) \
    asm volatile("cp.async.bulk.tensor.2d.shared::cta.global.tile.mbarrier::complete_tx::bytes " \
                 "[%0], [%1, {%2, %3}], [%4];" \
                 :: "r"(smem), "l"(tmap), "r"(cx), "r"(cy), "r"(mbar) : "memory")

// ---------------- tcgen05 tf32 GEMM, TMA-fed, single-thread control ----------
template<int NS, int NMAT>
__device__ __forceinline__ void gemm_tma(const CUtensorMap* tA, const CUtensorMap* tW,
                                         int wrow0,
                                         float* C0, float* C1, float* C2,
                                         const float* bias, int mode) {
    extern __shared__ char smem[];
    const int tid = threadIdx.x;
    const int wid = tid >> 5;
    const int lane = tid & 31;
    const int row0 = blockIdx.x * BM, col0 = blockIdx.y * BN;
    const uint32_t sbase = smem_u32(smem);
    const int STG = 16384 * (1 + NMAT);
    const int ACOLS = (NMAT == 1) ? 128 : 512;

    if (wid == 0) TC_ALLOC(sbase, ACOLS);
    if (tid < 16)       MBAR_INIT(sbase + 8 + tid * 8, 1);            // full[c]
    else if (tid < 32)  MBAR_INIT(sbase + 136 + (tid - 16) * 8, 1);   // mma[c]
    FENCE_ASYNC();
    __syncthreads();
    uint32_t tmem;
    asm volatile("ld.shared.b32 %0, [%1];" : "=r"(tmem) : "r"(sbase));

    if (tid == 0) {
        // prologue: stages 0..NS-2 in flight
#pragma unroll
        for (int s = 0; s < NS - 1; s++) {
            const uint32_t st = sbase + SMEM_TILE0 + s * STG;
            MBAR_EXPECT(sbase + 8 + s * 8, (uint32_t)STG);
            TMA_2D(st, tA, s * BKC, row0, sbase + 8 + s * 8);
#pragma unroll
            for (int m = 0; m < NMAT; m++)
                TMA_2D(st + 16384 * (1 + m), tW, s * BKC, wrow0 + m * DIM + col0,
                       sbase + 8 + s * 8);
        }
        for (int c = 0; c < NCHUNK; c++) {
            const int s = c + NS - 1;
            if (s < NCHUNK) {
                if (s >= NS) mbar_wait(sbase + 136 + (s - NS) * 8, 0);  // buffer free
                const uint32_t st = sbase + SMEM_TILE0 + (s % NS) * STG;
                MBAR_EXPECT(sbase + 8 + s * 8, (uint32_t)STG);
                TMA_2D(st, tA, s * BKC, row0, sbase + 8 + s * 8);
#pragma unroll
                for (int m = 0; m < NMAT; m++)
                    TMA_2D(st + 16384 * (1 + m), tW, s * BKC, wrow0 + m * DIM + col0,
                           sbase + 8 + s * 8);
            }
            mbar_wait(sbase + 8 + c * 8, 0);                            // full[c]
            const uint32_t st = sbase + SMEM_TILE0 + (c % NS) * STG;
            uint64_t ad = make_desc(st);
#pragma unroll
            for (int m = 0; m < NMAT; m++) {
                uint64_t bd = make_desc(st + 16384 * (1 + m));
#pragma unroll
                for (int s4 = 0; s4 < 4; s4++)
                    mma_tf32(tmem + m * 128, ad + s4 * 2, bd + s4 * 2,
                             (uint32_t)(c * 4 + s4 > 0));
            }
            COMMIT_CG1(sbase + 136 + c * 8);                            // mma[c]
        }
    }
    mbar_wait(sbase + 136 + (NCHUNK - 1) * 8, 0);   // all threads: MMAs done

    TC_FENCE_AFTER();
    float* Cs[3] = {C0, C1, C2};
    if (wid < 4) {
        const int r = row0 + wid * 32 + lane;
#pragma unroll
        for (int m = 0; m < NMAT; m++) {
            float* C = Cs[m];
#pragma unroll
            for (int cb = 0; cb < 4; cb++) {
                uint32_t rg[32];
                LDTM_X32(rg, tmem + m * 128 + cb * 32);
                TC_WAIT_LD();
                if (r < ROWS) {
                    float* outp = &C[(size_t)r * DIM + col0 + cb * 32];
#pragma unroll
                    for (int j = 0; j < 8; j++) {
                        float4 v;
                        v.x = __uint_as_float(rg[j * 4 + 0]);
                        v.y = __uint_as_float(rg[j * 4 + 1]);
                        v.z = __uint_as_float(rg[j * 4 + 2]);
                        v.w = __uint_as_float(rg[j * 4 + 3]);
                        if (mode == 1) {
                            float4 old = *(float4*)&outp[j * 4];
                            const float4 bv = *(const float4*)&bias[col0 + cb * 32 + j * 4];
                            v.x += old.x + bv.x; v.y += old.y + bv.y;
                            v.z += old.z + bv.z; v.w += old.w + bv.w;
                        }
                        *(float4*)&outp[j * 4] = v;
                    }
                }
            }
        }
    }
    TC_FENCE_BEFORE();
    __syncthreads();
    if (wid == 0) TC_DEALLOC(tmem, ACOLS);
}

#else  /* !HAS_TCGEN05: compile-only fallback for the non-'a' PTX pass */

template<int NS, int NMAT>
__device__ __forceinline__ void gemm_tma(const CUtensorMap* tA, const CUtensorMap* tW,
                                         int wrow0,
                                         float* C0, float* C1, float* C2,
                                         const float* bias, int mode) {
    const int tid = threadIdx.x;
    const int row0 = blockIdx.x * BM, col0 = blockIdx.y * BN;
    const int r = row0 + (tid >> 1);
    const int c0 = col0 + (tid & 1) * 64;
    if (r >= ROWS) return;
    const float* A = (mode == 1) ? g_A : (const float*)C0;  // unused path on GB300
    float* Cs[3] = {C0, C1, C2};
    for (int m = 0; m < NMAT; m++) {
        const float* Bt = g_Wt + (size_t)(wrow0 + m * DIM) * DIM;
        for (int cc = 0; cc < 64; cc++) {
            int c = c0 + cc;
            float s = 0.f;
            for (int k = 0; k < DIM; k++) s += A[(size_t)r * DIM + k] * Bt[(size_t)c * DIM + k];
            size_t o = (size_t)r * DIM + c;
            if (mode == 0) Cs[m][o] = s;
            else           Cs[m][o] += s + bias[c];
        }
    }
}
#endif  /* HAS_TCGEN05 */

__global__ void k_gemm_qkv(const __grid_constant__ CUtensorMap tmA,
                           const __grid_constant__ CUtensorMap tmW, int layer) {
    gemm_tma<3, 3>(&tmA, &tmW, layer * 4 * DIM, g_Q, g_K, g_V, nullptr, 0);
}

__global__ void k_gemm_resid(const __grid_constant__ CUtensorMap tmA,
                             const __grid_constant__ CUtensorMap tmW, int layer,
                             const float* __restrict__ bo, float* __restrict__ X) {
    gemm_tma<6, 1>(&tmA, &tmW, (layer * 4 + 3) * DIM, X, nullptr, nullptr, bo, 1);
}

// ---------------- Axial attention: parallel softmax (64-lane reduce) ----------
__global__ void k_axial(int typ) {
    const int n = blockIdx.x;
    const int head = blockIdx.y;
    const int b = blockIdx.z;
    __shared__ float Ks[49][65];
    __shared__ float Vs[49][65];
    __shared__ float Qs[2][64];
    __shared__ float sc[2][64];
    __shared__ float rmax[2][2];
    __shared__ float rsum[2][2];
    const int tid = threadIdx.x;

    for (int idx = tid; idx < 49 * 64; idx += 128) {
        int j = idx >> 6, d = idx & 63;
        int pos = (j == 0) ? 0 : (typ == 0 ? 1 + n * GWID + (j - 1)
                                           : 1 + (j - 1) * GWID + n);
        size_t o = ((size_t)(b * SEQ + pos)) * DIM + head * DHEAD + d;
        Ks[j][d] = g_K[o];
        Vs[j][d] = g_V[o];
    }
    __syncthreads();

    const int sub = tid >> 6;
    const int l = tid & 63;
    const int w = (tid >> 5) & 1;
    for (int q0 = 0; q0 < 49; q0 += 2) {
        int qi = q0 + sub;
        bool act = (qi < 49);
        int qpos = 0;
        if (act) {
            qpos = (qi == 0) ? 0 : (typ == 0 ? 1 + n * GWID + (qi - 1)
                                             : 1 + (qi - 1) * GWID + n);
            Qs[sub][l] = g_Q[((size_t)(b * SEQ + qpos)) * DIM + head * DHEAD + l];
        }
        __syncthreads();
        float s = -FLT_MAX;
        if (act && l <= qi) {
            float acc = 0.f;
#pragma unroll 16
            for (int d = 0; d < 64; d++) acc += Qs[sub][d] * Ks[l][d];
            s = acc * 0.125f;
        }
        float m = s;
        for (int off = 16; off; off >>= 1) m = fmaxf(m, __shfl_xor_sync(0xffffffffu, m, off));
        if ((tid & 31) == 0) rmax[sub][w] = m;
        __syncthreads();
        m = fmaxf(rmax[sub][0], rmax[sub][1]);
        float pv = (act && l <= qi) ? expf(s - m) : 0.0f;
        float su = pv;
        for (int off = 16; off; off >>= 1) su += __shfl_xor_sync(0xffffffffu, su, off);
        if ((tid & 31) == 0) rsum[sub][w] = su;
        __syncthreads();
        su = rsum[sub][0] + rsum[sub][1];
        sc[sub][l] = pv / su;
        __syncthreads();
        if (act && !(qi == 0 && n != 0)) {
            float o = 0.f;
            for (int j = 0; j <= qi; j++) o += sc[sub][j] * Vs[j][l];
            g_A[((size_t)(b * SEQ + qpos)) * DIM + head * DHEAD + l] = o;
        }
        __syncthreads();
    }
}

// ---------------- Nearby attention, tiled: CTA = (b, head, t, 2-row h-band) ----
#define KSTRIDE 65
#define NB_KOFF 0
#define NB_VOFF (384*KSTRIDE)
#define NB_QOFF (2*384*KSTRIDE)
#define NB_POFF (NB_QOFF + 8*64)
#define NB_ROFF (NB_POFF + 8*128)
#define NB_SMEM_FLOATS (NB_ROFF + 8*128)
#define NB_SMEM_BYTES (NB_SMEM_FLOATS*4)   /* 209920 */

__global__ void k_nearby_t() {
    extern __shared__ float sm[];
    const int tid = threadIdx.x;
    const int wid = tid >> 5;
    const int lane = tid & 31;
    const int t = blockIdx.y;
    const int h0 = blockIdx.x * 2;
    const int b = blockIdx.z >> 3;
    const int head = blockIdx.z & 7;
    const size_t base = ((size_t)b * SEQ) * DIM + head * DHEAD;
    const int t0 = max(0, t - 3);
    const int nf = t - t0 + 1;

    const int nchunks = nf * 96 * 16;
    for (int idx = tid; idx < nchunks; idx += 256) {
        const int row = idx >> 4, c4 = idx & 15;
        const int f = row / 96, rem = row % 96;
        const int hloc = rem >> 4, wk = rem & 15;
        const int hk = h0 - 2 + hloc;
        if (hk >= 0 && hk < 16) {
            const int kp = 1 + (t0 + f) * 256 + hk * 16 + wk;
            const size_t go = base + (size_t)kp * DIM + c4 * 4;
            float4 kv = *(const float4*)&g_K[go];
            float4 vv = *(const float4*)&g_V[go];
            float* kd = &sm[NB_KOFF + row * KSTRIDE + c4 * 4];
            float* vd = &sm[NB_VOFF + row * KSTRIDE + c4 * 4];
            kd[0] = kv.x; kd[1] = kv.y; kd[2] = kv.z; kd[3] = kv.w;
            vd[0] = vv.x; vd[1] = vv.y; vd[2] = vv.z; vd[3] = vv.w;
        }
    }
    __syncthreads();

    float* qsh = &sm[NB_QOFF + wid * 64];
    float* psh = &sm[NB_POFF + wid * 128];
    int*   rsh = (int*)&sm[NB_ROFF + wid * 128];

    for (int j = 0; j < 4; j++) {
        const int q = wid + 8 * j;
        const int qh_off = q >> 4, qw = q & 15;
        const int h = h0 + qh_off;
        const int i = t * 256 + h * 16 + qw;

        if (i == 0) {
            float* out0 = &g_A[base];
            out0[lane]      = g_V[base + lane];
            out0[lane + 32] = g_V[base + lane + 32];
            float a0 = 0.f, a1 = 0.f;
            for (int r = 0; r < SEQ; r++) {
                a0 += g_V[base + (size_t)r * DIM + lane];
                a1 += g_V[base + (size_t)r * DIM + lane + 32];
            }
            const float inv = 1.0f / (float)SEQ;
            float* outU = &g_A[base + (size_t)S_IMG * DIM];
            outU[lane]      = a0 * inv;
            outU[lane + 32] = a1 * inv;
            continue;
        }
        const int p = i;
        qsh[lane]      = g_Q[base + (size_t)p * DIM + lane];
        qsh[lane + 32] = g_Q[base + (size_t)p * DIM + lane + 32];
        __syncwarp();

        const int nslots = nf * 25;
        float sloc[4]; int myrow[4];
#pragma unroll
        for (int s = 0; s < 4; s++) {
            const int slot = lane + 32 * s;
            float scv = -FLT_MAX; int r = -1;
            if (slot < nslots) {
                const int f = slot / 25, rr = slot % 25;
                const int dh = rr / 5, dw = rr % 5;
                const int tk = t0 + f;
                const int hk = h - 2 + dh, wk = qw - 2 + dw;
                if (hk >= 0 && hk < 16 && wk >= 0 && wk < 16 &&
                    (tk < t || rr < 12)) {
                    r = f * 96 + (qh_off + dh) * 16 + wk;
                    const float* kr = &sm[NB_KOFF + r * KSTRIDE];
                    float acc = 0.f;
#pragma unroll 16
                    for (int d = 0; d < 64; d++) acc += qsh[d] * kr[d];
                    scv = acc * 0.125f;
                }
            }
            sloc[s] = scv; myrow[s] = r;
            if (slot < 128) rsh[slot] = r;
        }
        float m = fmaxf(fmaxf(sloc[0], sloc[1]), fmaxf(sloc[2], sloc[3]));
        for (int off = 16; off; off >>= 1) m = fmaxf(m, __shfl_xor_sync(0xffffffffu, m, off));
        float sum = 0.f;
#pragma unroll
        for (int s = 0; s < 4; s++) {
            const int slot = lane + 32 * s;
            float pv = (myrow[s] >= 0) ? expf(sloc[s] - m) : 0.0f;
            if (slot < 128) psh[slot] = pv;
            sum += pv;
        }
        for (int off = 16; off; off >>= 1) sum += __shfl_xor_sync(0xffffffffu, sum, off);
        const float inv = 1.0f / sum;
        __syncwarp();

        float o0 = 0.f, o1 = 0.f;
        for (int slot = 0; slot < nslots; slot++) {
            const int r = rsh[slot];
            if (r < 0) continue;
            const float pv = psh[slot];
            const float* vr = &sm[NB_VOFF + r * KSTRIDE];
            o0 += pv * vr[lane];
            o1 += pv * vr[lane + 32];
        }
        g_A[base + (size_t)p * DIM + lane]      = o0 * inv;
        g_A[base + (size_t)p * DIM + lane + 32] = o1 * inv;
        __syncwarp();
    }
}

// ---------------- host: tensor map construction ----------------
typedef CUresult (*PFN_tmEncode)(CUtensorMap*, CUtensorMapDataType, cuuint32_t, void*,
                                 const cuuint64_t*, const cuuint64_t*,
                                 const cuuint32_t*, const cuuint32_t*,
                                 CUtensorMapInterleave, CUtensorMapSwizzle,
                                 CUtensorMapL2promotion, CUtensorMapFloatOOBfill);

static void make_tm(PFN_tmEncode enc, CUtensorMap* tm, void* ptr,
                    unsigned long long d0, unsigned long long d1) {
    cuuint64_t dims[2] = {d0, d1};
    cuuint64_t strides[1] = {d0 * 4};
    cuuint32_t box[2] = {32, 128};
    cuuint32_t es[2] = {1, 1};
    enc(tm, CU_TENSOR_MAP_DATA_TYPE_FLOAT32, 2, ptr, dims, strides, box, es,
        CU_TENSOR_MAP_INTERLEAVE_NONE, CU_TENSOR_MAP_SWIZZLE_128B,
        CU_TENSOR_MAP_L2_PROMOTION_L2_128B, CU_TENSOR_MAP_FLOAT_OOB_FILL_NONE);
}

// ---------------- driver ----------------
extern "C" void kernel_launch(void* const* d_in, const int* in_sizes, int n_in,
                              void* d_out, int out_size) {
    const float* x = (const float*)d_in[0];
    float* X = (float*)d_out;

    cudaFuncSetAttribute(k_gemm_qkv, cudaFuncAttributeMaxDynamicSharedMemorySize, SMEM_Q_TOTAL);
    cudaFuncSetAttribute(k_gemm_resid, cudaFuncAttributeMaxDynamicSharedMemorySize, SMEM_R_TOTAL);
    cudaFuncSetAttribute(k_nearby_t, cudaFuncAttributeMaxDynamicSharedMemorySize, NB_SMEM_BYTES);

    void* fn = nullptr;
    cudaDriverEntryPointQueryResult qr;
    cudaGetDriverEntryPointByVersion("cuTensorMapEncodeTiled", &fn, 12000,
                                     cudaEnableDefault, &qr);
    PFN_tmEncode enc = (PFN_tmEncode)fn;
    void *pA = nullptr, *pW = nullptr;
    cudaGetSymbolAddress(&pA, g_A);
    cudaGetSymbolAddress(&pW, g_Wt);
    CUtensorMap tmX, tmA, tmW;
    make_tm(enc, &tmX, X, DIM, ROWS);
    make_tm(enc, &tmA, pA, DIM, ROWS);
    make_tm(enc, &tmW, pW, DIM, 12 * DIM);

    cudaMemcpyAsync(X, x, sizeof(float) * (size_t)ROWS * DIM,
                    cudaMemcpyDeviceToDevice, 0);

    k_transpose<<<dim3(16, 16, 12), dim3(32, 8)>>>(
        (const float*)d_in[2],  (const float*)d_in[3],  (const float*)d_in[4],  (const float*)d_in[5],
        (const float*)d_in[7],  (const float*)d_in[8],  (const float*)d_in[9],  (const float*)d_in[10],
        (const float*)d_in[12], (const float*)d_in[13], (const float*)d_in[14], (const float*)d_in[15]);

    dim3 gg((ROWS + BM - 1) / BM, DIM / BN);   // 37 x 4 = 148 CTAs
    for (int l = 0; l < 3; l++) {
        const float* bo = (const float*)d_in[2 + l * 5 + 4];
        k_gemm_qkv<<<gg, 256, SMEM_Q_TOTAL>>>(tmX, tmW, l);
        if (l < 2) k_axial<<<dim3(48, 8, 2), 128>>>(l);
        else       k_nearby_t<<<dim3(8, 9, 16), 256, NB_SMEM_BYTES>>>();
        k_gemm_resid<<<gg, 256, SMEM_R_TOTAL>>>(tmA, tmW, l, bo, X);
    }
}

// round 14
// speedup vs baseline: 4.5428x; 1.0340x over previous
#include <cuda_runtime.h>
#include <cuda.h>
#include <math.h>
#include <float.h>
#include <stdint.h>

#define BB 2
#define SEQ 2305
#define S_IMG 2304
#define DIM 512
#define HEADS 8
#define DHEAD 64
#define ROWS (BB*SEQ)   /* 4610 */
#define GWID 48

#define BM 128
#define BN 128
#define BKC 32              /* k per smem chunk */
#define NCHUNK (DIM/BKC)    /* 16 */

// tcgen05 available only in the arch-specific ('a') compilation pass.
#if !defined(__CUDA_ARCH__) || defined(__CUDA_ARCH_FEAT_SM103_ALL) || defined(__CUDA_ARCH_FEAT_SM100_ALL) || defined(__CUDA_ARCH_FEAT_SM101_ALL)
#define HAS_TCGEN05 1
#else
#define HAS_TCGEN05 0
#endif

__device__ __align__(1024) float g_Q[ROWS*DIM];
__device__ __align__(1024) float g_K[ROWS*DIM];
__device__ __align__(1024) float g_V[ROWS*DIM];
__device__ __align__(1024) float g_A[ROWS*DIM];
__device__ __align__(1024) float g_Wt[12*DIM*DIM];   /* transposed weights [n][k] */

// SMEM header: [0:4) tmem ptr, [8:136) 16 full mbars, [136:264) 16 mma mbars
#define SMEM_TILE0 1024
#define SMEM_Q_TOTAL (1024 + 3*4*16384)   /* NS=3, stage 64KB -> 197632 */
#define SMEM_R_TOTAL (1024 + 6*2*16384)   /* NS=6, stage 32KB -> 197632 */

// ---------------- weight transpose: g_Wt[m][n][k] = W_m[k][n] ----------------
__global__ void k_transpose(const float* w0, const float* w1, const float* w2,
                            const float* w3, const float* w4, const float* w5,
                            const float* w6, const float* w7, const float* w8,
                            const float* w9, const float* w10, const float* w11) {
    const float* ws[12] = {w0,w1,w2,w3,w4,w5,w6,w7,w8,w9,w10,w11};
    const float* W = ws[blockIdx.z];
    float* out = g_Wt + (size_t)blockIdx.z * DIM * DIM;
    __shared__ float t[32][33];
    const int nx = blockIdx.x * 32, ky = blockIdx.y * 32;
#pragma unroll
    for (int j = 0; j < 4; j++) {
        int k = ky + threadIdx.y + j * 8;
        t[threadIdx.y + j * 8][threadIdx.x] = W[(size_t)k * DIM + nx + threadIdx.x];
    }
    __syncthreads();
#pragma unroll
    for (int j = 0; j < 4; j++) {
        int n = nx + threadIdx.y + j * 8;
        out[(size_t)n * DIM + ky + threadIdx.x] = t[threadIdx.x][threadIdx.y + j * 8];
    }
}

#if HAS_TCGEN05
// ---------------- tcgen05 / TMA helpers ----------------
__device__ __forceinline__ uint32_t smem_u32(const void* p) {
    uint32_t a;
    asm("{ .reg .u64 t; cvta.to.shared.u64 t, %1; cvt.u32.u64 %0, t; }" : "=r"(a) : "l"(p));
    return a;
}
static __device__ __forceinline__ uint64_t make_desc(uint32_t addr) {
    const uint64_t base = (uint64_t(2) << 61) | (uint64_t(1) << 46) |
                          (uint64_t(64) << 32) | (uint64_t(1) << 16);
    return base | ((uint64_t)(addr >> 4) & 0x3FFF);
}
#define IDESC_TF32 ((1u<<4) | (2u<<7) | (2u<<10) | ((BN/8u)<<17) | ((BM/16u)<<24))

__device__ __forceinline__ void mma_tf32(uint32_t d_tmem, uint64_t a_desc,
                                         uint64_t b_desc, uint32_t en) {
    asm volatile(
        "{\n\t.reg .pred p;\n\t"
        "setp.ne.u32 p, %4, 0;\n\t"
        "tcgen05.mma.cta_group::1.kind::tf32 [%0], %1, %2, %3, {%5,%5,%5,%5}, p;\n\t}"
        :: "r"(d_tmem), "l"(a_desc), "l"(b_desc), "r"(IDESC_TF32), "r"(en), "r"(0u)
        : "memory");
}
#define MBAR_INIT(a,c)  asm volatile("mbarrier.init.shared.b64 [%0], %1;" :: "r"(a), "r"(c) : "memory")
#define MBAR_EXPECT(a,b) asm volatile("mbarrier.arrive.expect_tx.shared.b64 _, [%0], %1;" :: "r"(a), "r"(b) : "memory")
#define COMMIT_CG1(a)   asm volatile("tcgen05.commit.cta_group::1.mbarrier::arrive::one.shared::cluster.b64 [%0];" :: "r"(a) : "memory")
__device__ __forceinline__ void mbar_wait(uint32_t addr, uint32_t parity) {
    asm volatile(
        "{\n\t.reg .pred P1;\n\t"
        "WL_%=:\n\t"
        "mbarrier.try_wait.parity.acquire.cta.shared::cta.b64 P1, [%0], %1, 0x989680;\n\t"
        "@P1 bra.uni WD_%=;\n\t"
        "bra.uni WL_%=;\n\t"
        "WD_%=:\n\t}"
        :: "r"(addr), "r"(parity) : "memory");
}
#define FENCE_ASYNC()   asm volatile("fence.proxy.async.shared::cta;" ::: "memory")
#define TC_ALLOC(sp,n)  asm volatile("tcgen05.alloc.cta_group::1.sync.aligned.shared::cta.b32 [%0], %1;" :: "r"(sp), "r"(n) : "memory")
#define TC_DEALLOC(t,n) asm volatile("tcgen05.dealloc.cta_group::1.sync.aligned.b32 %0, %1;" :: "r"(t), "r"(n))
#define TC_FENCE_AFTER()  asm volatile("tcgen05.fence::after_thread_sync;" ::: "memory")
#define TC_FENCE_BEFORE() asm volatile("tcgen05.fence::before_thread_sync;" ::: "memory")
#define TC_WAIT_LD()      asm volatile("tcgen05.wait::ld.sync.aligned;" ::: "memory")
#define LDTM_X32(r, a) \
    asm volatile("tcgen05.ld.sync.aligned.32x32b.x32.b32 " \
        "{%0,%1,%2,%3,%4,%5,%6,%7,%8,%9,%10,%11,%12,%13,%14,%15," \
        "%16,%17,%18,%19,%20,%21,%22,%23,%24,%25,%26,%27,%28,%29,%30,%31}, [%32];" \
        : "=r"((r)[0]),"=r"((r)[1]),"=r"((r)[2]),"=r"((r)[3]),"=r"((r)[4]),"=r"((r)[5]),"=r"((r)[6]),"=r"((r)[7]), \
          "=r"((r)[8]),"=r"((r)[9]),"=r"((r)[10]),"=r"((r)[11]),"=r"((r)[12]),"=r"((r)[13]),"=r"((r)[14]),"=r"((r)[15]), \
          "=r"((r)[16]),"=r"((r)[17]),"=r"((r)[18]),"=r"((r)[19]),"=r"((r)[20]),"=r"((r)[21]),"=r"((r)[22]),"=r"((r)[23]), \
          "=r"((r)[24]),"=r"((r)[25]),"=r"((r)[26]),"=r"((r)[27]),"=r"((r)[28]),"=r"((r)[29]),"=r"((r)[30]),"=r"((r)[31]) \
        : "r"(a))
#define TMA_2D(smem, tmap, cx, cy, mbar) \
    asm volatile("cp.async.bulk.tensor.2d.shared::cta.global.tile.mbarrier::complete_tx::bytes " \
                 "[%0], [%1, {%2, %3}], [%4];" \
                 :: "r"(smem), "l"(tmap), "r"(cx), "r"(cy), "r"(mbar) : "memory")

// ---------------- tcgen05 tf32 GEMM, TMA-fed, single-thread control ----------
template<int NS, int NMAT>
__device__ __forceinline__ void gemm_tma(const CUtensorMap* tA, const CUtensorMap* tW,
                                         int wrow0,
                                         float* C0, float* C1, float* C2,
                                         const float* bias, int mode) {
    extern __shared__ char smem[];
    const int tid = threadIdx.x;
    const int wid = tid >> 5;
    const int lane = tid & 31;
    const int row0 = blockIdx.x * BM, col0 = blockIdx.y * BN;
    const uint32_t sbase = smem_u32(smem);
    const int STG = 16384 * (1 + NMAT);
    const int ACOLS = (NMAT == 1) ? 128 : 512;

    if (wid == 0) TC_ALLOC(sbase, ACOLS);
    if (tid < 16)       MBAR_INIT(sbase + 8 + tid * 8, 1);            // full[c]
    else if (tid < 32)  MBAR_INIT(sbase + 136 + (tid - 16) * 8, 1);   // mma[c]
    FENCE_ASYNC();
    __syncthreads();
    uint32_t tmem;
    asm volatile("ld.shared.b32 %0, [%1];" : "=r"(tmem) : "r"(sbase));

    if (tid == 0) {
        // prologue: stages 0..NS-2 in flight
#pragma unroll
        for (int s = 0; s < NS - 1; s++) {
            const uint32_t st = sbase + SMEM_TILE0 + s * STG;
            MBAR_EXPECT(sbase + 8 + s * 8, (uint32_t)STG);
            TMA_2D(st, tA, s * BKC, row0, sbase + 8 + s * 8);
#pragma unroll
            for (int m = 0; m < NMAT; m++)
                TMA_2D(st + 16384 * (1 + m), tW, s * BKC, wrow0 + m * DIM + col0,
                       sbase + 8 + s * 8);
        }
        for (int c = 0; c < NCHUNK; c++) {
            const int s = c + NS - 1;
            if (s < NCHUNK) {
                if (s >= NS) mbar_wait(sbase + 136 + (s - NS) * 8, 0);  // buffer free
                const uint32_t st = sbase + SMEM_TILE0 + (s % NS) * STG;
                MBAR_EXPECT(sbase + 8 + s * 8, (uint32_t)STG);
                TMA_2D(st, tA, s * BKC, row0, sbase + 8 + s * 8);
#pragma unroll
                for (int m = 0; m < NMAT; m++)
                    TMA_2D(st + 16384 * (1 + m), tW, s * BKC, wrow0 + m * DIM + col0,
                           sbase + 8 + s * 8);
            }
            mbar_wait(sbase + 8 + c * 8, 0);                            // full[c]
            const uint32_t st = sbase + SMEM_TILE0 + (c % NS) * STG;
            uint64_t ad = make_desc(st);
#pragma unroll
            for (int m = 0; m < NMAT; m++) {
                uint64_t bd = make_desc(st + 16384 * (1 + m));
#pragma unroll
                for (int s4 = 0; s4 < 4; s4++)
                    mma_tf32(tmem + m * 128, ad + s4 * 2, bd + s4 * 2,
                             (uint32_t)(c * 4 + s4 > 0));
            }
            COMMIT_CG1(sbase + 136 + c * 8);                            // mma[c]
        }
    }
    mbar_wait(sbase + 136 + (NCHUNK - 1) * 8, 0);   // all threads: MMAs done

    TC_FENCE_AFTER();
    float* Cs[3] = {C0, C1, C2};
    if (wid < 4) {
        const int r = row0 + wid * 32 + lane;
#pragma unroll
        for (int m = 0; m < NMAT; m++) {
            float* C = Cs[m];
#pragma unroll
            for (int cb = 0; cb < 4; cb++) {
                uint32_t rg[32];
                LDTM_X32(rg, tmem + m * 128 + cb * 32);
                TC_WAIT_LD();
                if (r < ROWS) {
                    float* outp = &C[(size_t)r * DIM + col0 + cb * 32];
#pragma unroll
                    for (int j = 0; j < 8; j++) {
                        float4 v;
                        v.x = __uint_as_float(rg[j * 4 + 0]);
                        v.y = __uint_as_float(rg[j * 4 + 1]);
                        v.z = __uint_as_float(rg[j * 4 + 2]);
                        v.w = __uint_as_float(rg[j * 4 + 3]);
                        if (mode == 1) {
                            float4 old = *(float4*)&outp[j * 4];
                            const float4 bv = *(const float4*)&bias[col0 + cb * 32 + j * 4];
                            v.x += old.x + bv.x; v.y += old.y + bv.y;
                            v.z += old.z + bv.z; v.w += old.w + bv.w;
                        }
                        *(float4*)&outp[j * 4] = v;
                    }
                }
            }
        }
    }
    TC_FENCE_BEFORE();
    __syncthreads();
    if (wid == 0) TC_DEALLOC(tmem, ACOLS);
}

#else  /* !HAS_TCGEN05: compile-only fallback for the non-'a' PTX pass */

template<int NS, int NMAT>
__device__ __forceinline__ void gemm_tma(const CUtensorMap* tA, const CUtensorMap* tW,
                                         int wrow0,
                                         float* C0, float* C1, float* C2,
                                         const float* bias, int mode) {
    const int tid = threadIdx.x;
    const int row0 = blockIdx.x * BM, col0 = blockIdx.y * BN;
    const int r = row0 + (tid >> 1);
    const int c0 = col0 + (tid & 1) * 64;
    if (r >= ROWS) return;
    const float* A = (mode == 1) ? g_A : (const float*)C0;  // unused path on GB300
    float* Cs[3] = {C0, C1, C2};
    for (int m = 0; m < NMAT; m++) {
        const float* Bt = g_Wt + (size_t)(wrow0 + m * DIM) * DIM;
        for (int cc = 0; cc < 64; cc++) {
            int c = c0 + cc;
            float s = 0.f;
            for (int k = 0; k < DIM; k++) s += A[(size_t)r * DIM + k] * Bt[(size_t)c * DIM + k];
            size_t o = (size_t)r * DIM + c;
            if (mode == 0) Cs[m][o] = s;
            else           Cs[m][o] += s + bias[c];
        }
    }
}
#endif  /* HAS_TCGEN05 */

__global__ void k_gemm_qkv(const __grid_constant__ CUtensorMap tmA,
                           const __grid_constant__ CUtensorMap tmW, int layer) {
    gemm_tma<3, 3>(&tmA, &tmW, layer * 4 * DIM, g_Q, g_K, g_V, nullptr, 0);
}

__global__ void k_gemm_resid(const __grid_constant__ CUtensorMap tmA,
                             const __grid_constant__ CUtensorMap tmW, int layer,
                             const float* __restrict__ bo, float* __restrict__ X) {
    gemm_tma<6, 1>(&tmA, &tmW, (layer * 4 + 3) * DIM, X, nullptr, nullptr, bo, 1);
}

// ---------------- Axial attention: warp-per-query, barrier-free main loop ----
__global__ void __launch_bounds__(256) k_axial(int typ) {
    const int n = blockIdx.x;      // 0..47
    const int head = blockIdx.y;   // 0..7
    const int b = blockIdx.z;      // 0..1
    __shared__ float Ks[49][65];
    __shared__ float Vs[49][65];
    __shared__ float Qs[49][65];
    __shared__ float psh[8][64];
    const int tid = threadIdx.x;   // 256
    const int wid = tid >> 5;
    const int lane = tid & 31;

    for (int idx = tid; idx < 49 * 64; idx += 256) {
        int j = idx >> 6, d = idx & 63;
        int pos = (j == 0) ? 0 : (typ == 0 ? 1 + n * GWID + (j - 1)
                                           : 1 + (j - 1) * GWID + n);
        size_t o = ((size_t)(b * SEQ + pos)) * DIM + head * DHEAD + d;
        Ks[j][d] = g_K[o];
        Vs[j][d] = g_V[o];
        Qs[j][d] = g_Q[o];
    }
    __syncthreads();

    for (int q = wid; q < 49; q += 8) {
        // scores for keys (lane) and (lane+32), causal j <= q
        float s0 = -FLT_MAX, s1 = -FLT_MAX;
        {
            float a0 = 0.f, a1 = 0.f;
#pragma unroll 16
            for (int d = 0; d < 64; d++) {
                const float qv = Qs[q][d];
                a0 += qv * Ks[lane][d];
                a1 += qv * Ks[lane + 32][d];
            }
            if (lane <= q)      s0 = a0 * 0.125f;
            if (lane + 32 <= q) s1 = a1 * 0.125f;
        }
        float m = fmaxf(s0, s1);
#pragma unroll
        for (int off = 16; off; off >>= 1) m = fmaxf(m, __shfl_xor_sync(0xffffffffu, m, off));
        const float p0 = (lane <= q)      ? expf(s0 - m) : 0.f;
        const float p1 = (lane + 32 <= q) ? expf(s1 - m) : 0.f;
        float su = p0 + p1;
#pragma unroll
        for (int off = 16; off; off >>= 1) su += __shfl_xor_sync(0xffffffffu, su, off);
        const float inv = 1.0f / su;
        psh[wid][lane]      = p0 * inv;
        psh[wid][lane + 32] = p1 * inv;
        __syncwarp();
        if (!(q == 0 && n != 0)) {   // BOS written only from n==0 block
            float o0 = 0.f, o1 = 0.f;
            for (int j = 0; j <= q; j++) {
                const float pv = psh[wid][j];
                o0 += pv * Vs[j][lane];
                o1 += pv * Vs[j][lane + 32];
            }
            const int qpos = (q == 0) ? 0 : (typ == 0 ? 1 + n * GWID + (q - 1)
                                                      : 1 + (q - 1) * GWID + n);
            const size_t o = ((size_t)(b * SEQ + qpos)) * DIM + head * DHEAD;
            g_A[o + lane]      = o0;
            g_A[o + lane + 32] = o1;
        }
        __syncwarp();
    }
}

// ---------------- Nearby attention, tiled: CTA = (b, head, t, 2-row h-band) ----
#define KSTRIDE 65
#define NB_KOFF 0
#define NB_VOFF (384*KSTRIDE)
#define NB_QOFF (2*384*KSTRIDE)
#define NB_POFF (NB_QOFF + 8*64)
#define NB_ROFF (NB_POFF + 8*128)
#define NB_SMEM_FLOATS (NB_ROFF + 8*128)
#define NB_SMEM_BYTES (NB_SMEM_FLOATS*4)   /* 209920 */

__global__ void k_nearby_t() {
    extern __shared__ float sm[];
    const int tid = threadIdx.x;
    const int wid = tid >> 5;
    const int lane = tid & 31;
    const int t = blockIdx.y;
    const int h0 = blockIdx.x * 2;
    const int b = blockIdx.z >> 3;
    const int head = blockIdx.z & 7;
    const size_t base = ((size_t)b * SEQ) * DIM + head * DHEAD;
    const int t0 = max(0, t - 3);
    const int nf = t - t0 + 1;

    const int nchunks = nf * 96 * 16;
    for (int idx = tid; idx < nchunks; idx += 256) {
        const int row = idx >> 4, c4 = idx & 15;
        const int f = row / 96, rem = row % 96;
        const int hloc = rem >> 4, wk = rem & 15;
        const int hk = h0 - 2 + hloc;
        if (hk >= 0 && hk < 16) {
            const int kp = 1 + (t0 + f) * 256 + hk * 16 + wk;
            const size_t go = base + (size_t)kp * DIM + c4 * 4;
            float4 kv = *(const float4*)&g_K[go];
            float4 vv = *(const float4*)&g_V[go];
            float* kd = &sm[NB_KOFF + row * KSTRIDE + c4 * 4];
            float* vd = &sm[NB_VOFF + row * KSTRIDE + c4 * 4];
            kd[0] = kv.x; kd[1] = kv.y; kd[2] = kv.z; kd[3] = kv.w;
            vd[0] = vv.x; vd[1] = vv.y; vd[2] = vv.z; vd[3] = vv.w;
        }
    }
    __syncthreads();

    float* qsh = &sm[NB_QOFF + wid * 64];
    float* psh = &sm[NB_POFF + wid * 128];
    int*   rsh = (int*)&sm[NB_ROFF + wid * 128];

    for (int j = 0; j < 4; j++) {
        const int q = wid + 8 * j;
        const int qh_off = q >> 4, qw = q & 15;
        const int h = h0 + qh_off;
        const int i = t * 256 + h * 16 + qw;
        if (i == 0) continue;          // specials handled cooperatively below
        const int p = i;
        qsh[lane]      = g_Q[base + (size_t)p * DIM + lane];
        qsh[lane + 32] = g_Q[base + (size_t)p * DIM + lane + 32];
        __syncwarp();

        const int nslots = nf * 25;
        float sloc[4]; int myrow[4];
#pragma unroll
        for (int s = 0; s < 4; s++) {
            const int slot = lane + 32 * s;
            float scv = -FLT_MAX; int r = -1;
            if (slot < nslots) {
                const int f = slot / 25, rr = slot % 25;
                const int dh = rr / 5, dw = rr % 5;
                const int tk = t0 + f;
                const int hk = h - 2 + dh, wk = qw - 2 + dw;
                if (hk >= 0 && hk < 16 && wk >= 0 && wk < 16 &&
                    (tk < t || rr < 12)) {
                    r = f * 96 + (qh_off + dh) * 16 + wk;
                    const float* kr = &sm[NB_KOFF + r * KSTRIDE];
                    float acc = 0.f;
#pragma unroll 16
                    for (int d = 0; d < 64; d++) acc += qsh[d] * kr[d];
                    scv = acc * 0.125f;
                }
            }
            sloc[s] = scv; myrow[s] = r;
            if (slot < 128) rsh[slot] = r;
        }
        float m = fmaxf(fmaxf(sloc[0], sloc[1]), fmaxf(sloc[2], sloc[3]));
        for (int off = 16; off; off >>= 1) m = fmaxf(m, __shfl_xor_sync(0xffffffffu, m, off));
        float sum = 0.f;
#pragma unroll
        for (int s = 0; s < 4; s++) {
            const int slot = lane + 32 * s;
            float pv = (myrow[s] >= 0) ? expf(sloc[s] - m) : 0.0f;
            if (slot < 128) psh[slot] = pv;
            sum += pv;
        }
        for (int off = 16; off; off >>= 1) sum += __shfl_xor_sync(0xffffffffu, sum, off);
        const float inv = 1.0f / sum;
        __syncwarp();

        float o0 = 0.f, o1 = 0.f;
        for (int slot = 0; slot < nslots; slot++) {
            const int r = rsh[slot];
            if (r < 0) continue;
            const float pv = psh[slot];
            const float* vr = &sm[NB_VOFF + r * KSTRIDE];
            o0 += pv * vr[lane];
            o1 += pv * vr[lane + 32];
        }
        g_A[base + (size_t)p * DIM + lane]      = o0 * inv;
        g_A[base + (size_t)p * DIM + lane + 32] = o1 * inv;
        __syncwarp();
    }

    // ---- specials, cooperative (block containing i==0 only): p=0 BOS copy,
    // ---- p=2304 = uniform mean over all SEQ rows
    if (t == 0 && h0 == 0) {
        __syncthreads();               // done reading staged K/V; reuse sm[0..255]
        if (tid < 64) g_A[base + tid] = g_V[base + tid];
        const int d = tid & 63, g = tid >> 6;   // 64 dims x 4 row-groups
        float acc = 0.f;
        for (int r = g; r < SEQ; r += 4)
            acc += g_V[base + (size_t)r * DIM + d];
        sm[g * 64 + d] = acc;
        __syncthreads();
        if (tid < 64) {
            const float s = sm[tid] + sm[64 + tid] + sm[128 + tid] + sm[192 + tid];
            g_A[base + (size_t)S_IMG * DIM + tid] = s * (1.0f / (float)SEQ);
        }
    }
}

// ---------------- host: tensor map construction ----------------
typedef CUresult (*PFN_tmEncode)(CUtensorMap*, CUtensorMapDataType, cuuint32_t, void*,
                                 const cuuint64_t*, const cuuint64_t*,
                                 const cuuint32_t*, const cuuint32_t*,
                                 CUtensorMapInterleave, CUtensorMapSwizzle,
                                 CUtensorMapL2promotion, CUtensorMapFloatOOBfill);

static void make_tm(PFN_tmEncode enc, CUtensorMap* tm, void* ptr,
                    unsigned long long d0, unsigned long long d1) {
    cuuint64_t dims[2] = {d0, d1};
    cuuint64_t strides[1] = {d0 * 4};
    cuuint32_t box[2] = {32, 128};
    cuuint32_t es[2] = {1, 1};
    enc(tm, CU_TENSOR_MAP_DATA_TYPE_FLOAT32, 2, ptr, dims, strides, box, es,
        CU_TENSOR_MAP_INTERLEAVE_NONE, CU_TENSOR_MAP_SWIZZLE_128B,
        CU_TENSOR_MAP_L2_PROMOTION_L2_128B, CU_TENSOR_MAP_FLOAT_OOB_FILL_NONE);
}

// ---------------- driver ----------------
extern "C" void kernel_launch(void* const* d_in, const int* in_sizes, int n_in,
                              void* d_out, int out_size) {
    const float* x = (const float*)d_in[0];
    float* X = (float*)d_out;

    cudaFuncSetAttribute(k_gemm_qkv, cudaFuncAttributeMaxDynamicSharedMemorySize, SMEM_Q_TOTAL);
    cudaFuncSetAttribute(k_gemm_resid, cudaFuncAttributeMaxDynamicSharedMemorySize, SMEM_R_TOTAL);
    cudaFuncSetAttribute(k_nearby_t, cudaFuncAttributeMaxDynamicSharedMemorySize, NB_SMEM_BYTES);

    void* fn = nullptr;
    cudaDriverEntryPointQueryResult qr;
    cudaGetDriverEntryPointByVersion("cuTensorMapEncodeTiled", &fn, 12000,
                                     cudaEnableDefault, &qr);
    PFN_tmEncode enc = (PFN_tmEncode)fn;
    void *pA = nullptr, *pW = nullptr;
    cudaGetSymbolAddress(&pA, g_A);
    cudaGetSymbolAddress(&pW, g_Wt);
    CUtensorMap tmX, tmA, tmW;
    make_tm(enc, &tmX, X, DIM, ROWS);
    make_tm(enc, &tmA, pA, DIM, ROWS);
    make_tm(enc, &tmW, pW, DIM, 12 * DIM);

    cudaMemcpyAsync(X, x, sizeof(float) * (size_t)ROWS * DIM,
                    cudaMemcpyDeviceToDevice, 0);

    k_transpose<<<dim3(16, 16, 12), dim3(32, 8)>>>(
        (const float*)d_in[2],  (const float*)d_in[3],  (const float*)d_in[4],  (const float*)d_in[5],
        (const float*)d_in[7],  (const float*)d_in[8],  (const float*)d_in[9],  (const float*)d_in[10],
        (const float*)d_in[12], (const float*)d_in[13], (const float*)d_in[14], (const float*)d_in[15]);

    dim3 gg((ROWS + BM - 1) / BM, DIM / BN);   // 37 x 4 = 148 CTAs
    for (int l = 0; l < 3; l++) {
        const float* bo = (const float*)d_in[2 + l * 5 + 4];
        k_gemm_qkv<<<gg, 256, SMEM_Q_TOTAL>>>(tmX, tmW, l);
        if (l < 2) k_axial<<<dim3(48, 8, 2), 256>>>(l);
        else       k_nearby_t<<<dim3(8, 9, 16), 256, NB_SMEM_BYTES>>>();
        k_gemm_resid<<<gg, 256, SMEM_R_TOTAL>>>(tmA, tmW, l, bo, X);
    }
}